// round 4
// baseline (speedup 1.0000x reference)
#include <cuda_runtime.h>
#include <cuda_bf16.h>
#include <cstdint>

// Problem constants
#define B_    32
#define S_    256
#define D_    256
#define U_    256
#define L_    16
#define DEG_  16
#define N_    (B_ * S_)        // 8192
#define E_    (N_ * DEG_)      // 131072

// ---------------------------------------------------------------------------
// Scratch (device globals: allocation-free rule)
// ---------------------------------------------------------------------------
__device__ float g_x[(size_t)N_ * D_];                    // [N,D] node features (b*S+s order)
__device__ float g_all_in [(size_t)L_ * N_ * U_];         // [L,N,U]
__device__ float g_all_out[(size_t)L_ * N_ * U_];         // [L,N,U]
__device__ float g_same[(size_t)N_ * U_];                 // [N,U]
__device__ float g_gin[N_], g_gout[N_], g_gloop[N_];      // per-node gate dot products
__device__ int   g_ein[E_], g_lin[E_], g_eout[E_], g_lout[E_];

// ---------------------------------------------------------------------------
// 1) x[n,d] = src[s,b,d] with n = b*S + s
// ---------------------------------------------------------------------------
__global__ void prep_x_kernel(const float* __restrict__ src) {
    int n = blockIdx.x;              // 0..N-1
    int s = n & (S_ - 1);
    int b = n >> 8;                  // n / S_
    int t = threadIdx.x;             // 0..255 = d
    g_x[(size_t)n * D_ + t] = src[(size_t)s * B_ * D_ + (size_t)b * D_ + t];
}

// ---------------------------------------------------------------------------
// 2) Edge index/label decode. JAX may materialize the declared-int64 arrays as
//    int32 (x64 disabled). Detect: int64 => odd 32-bit words of the first row
//    (values < 32) are all zero.
// ---------------------------------------------------------------------------
__device__ __forceinline__ int detect_is64(const int* p) {
    int z = 1;
    #pragma unroll
    for (int i = 1; i < 128; i += 2) z &= (p[i] == 0);
    return z;
}

__global__ void prep_edges_kernel(const void* __restrict__ arc_in,
                                  const void* __restrict__ lab_in,
                                  const void* __restrict__ arc_out,
                                  const void* __restrict__ lab_out) {
    __shared__ int s64;
    if (threadIdx.x == 0) s64 = detect_is64((const int*)arc_in);
    __syncthreads();
    int e = blockIdx.x * blockDim.x + threadIdx.x;
    if (e >= E_) return;
    int bi, si, li, bo, so, lo;
    if (s64) {
        const long long* ai = (const long long*)arc_in;
        const long long* ao = (const long long*)arc_out;
        bi = (int)ai[e];  si = (int)ai[E_ + e];  li = (int)((const long long*)lab_in)[e];
        bo = (int)ao[e];  so = (int)ao[E_ + e];  lo = (int)((const long long*)lab_out)[e];
    } else {
        const int* ai = (const int*)arc_in;
        const int* ao = (const int*)arc_out;
        bi = ai[e];  si = ai[E_ + e];  li = ((const int*)lab_in)[e];
        bo = ao[e];  so = ao[E_ + e];  lo = ((const int*)lab_out)[e];
    }
    g_ein[e]  = bi * S_ + si;  g_lin[e]  = li;
    g_eout[e] = bo * S_ + so;  g_lout[e] = lo;
}

// ---------------------------------------------------------------------------
// 3) Per-node gate dot products: gin = x.Vg_in, gout = x.Vg_out, gloop = x.Wg
//    One warp per node.
// ---------------------------------------------------------------------------
__global__ void gates_kernel(const float* __restrict__ vgin,
                             const float* __restrict__ vgout,
                             const float* __restrict__ wgloop) {
    int gid  = blockIdx.x * blockDim.x + threadIdx.x;
    int warp = gid >> 5;
    int lane = threadIdx.x & 31;
    if (warp >= N_) return;
    const float* xr = g_x + (size_t)warp * D_;
    float a = 0.f, b = 0.f, c = 0.f;
    #pragma unroll
    for (int d = lane; d < D_; d += 32) {
        float xv = xr[d];
        a += xv * vgin[d];
        b += xv * vgout[d];
        c += xv * wgloop[d];
    }
    #pragma unroll
    for (int off = 16; off; off >>= 1) {
        a += __shfl_xor_sync(0xffffffffu, a, off);
        b += __shfl_xor_sync(0xffffffffu, b, off);
        c += __shfl_xor_sync(0xffffffffu, c, off);
    }
    if (lane == 0) { g_gin[warp] = a; g_gout[warp] = b; g_gloop[warp] = c; }
}

// ---------------------------------------------------------------------------
// 4) Batched fp32 GEMM: C[bz] = x(8192x256) @ W[bz](256x256)
//    bz 0..15 -> V_in, 16..31 -> V_out, 32 -> W_self_loop
//    128x128 block tile, BK=8, 8x8 per thread, double-buffered smem.
// ---------------------------------------------------------------------------
__global__ void __launch_bounds__(256) gemm_kernel(const float* __restrict__ Vin,
                                                   const float* __restrict__ Vout,
                                                   const float* __restrict__ Wself) {
    const int bz = blockIdx.z;
    const float* Bm;
    float* C;
    if (bz < L_)            { Bm = Vin  + (size_t)bz * D_ * U_;        C = g_all_in  + (size_t)bz * N_ * U_; }
    else if (bz < 2 * L_)   { Bm = Vout + (size_t)(bz - L_) * D_ * U_; C = g_all_out + (size_t)(bz - L_) * N_ * U_; }
    else                    { Bm = Wself;                               C = g_same; }

    const int m0 = blockIdx.x * 128;
    const int n0 = blockIdx.y * 128;

    __shared__ float As[2][8][128];
    __shared__ float Bs[2][8][128];

    const int t    = threadIdx.x;
    const int arow = t >> 1,  acol = (t & 1) * 4;       // A: 128 rows x 8 k
    const int brow = t >> 5,  bcol = (t & 31) * 4;      // B: 8 k x 128 cols
    const int tm   = (t >> 4) * 8, tn = (t & 15) * 8;

    const float* Ag = g_x + (size_t)(m0 + arow) * D_ + acol;
    const float* Bg = Bm + (size_t)brow * U_ + n0 + bcol;

    float acc[8][8];
    #pragma unroll
    for (int i = 0; i < 8; i++)
        #pragma unroll
        for (int j = 0; j < 8; j++) acc[i][j] = 0.f;

    // prologue: tile 0
    {
        float4 a4 = *(const float4*)Ag;
        float4 b4 = *(const float4*)Bg;
        As[0][acol + 0][arow] = a4.x;
        As[0][acol + 1][arow] = a4.y;
        As[0][acol + 2][arow] = a4.z;
        As[0][acol + 3][arow] = a4.w;
        *(float4*)&Bs[0][brow][bcol] = b4;
    }
    __syncthreads();

    const int NT = D_ / 8;   // 32
    for (int kt = 0; kt < NT; kt++) {
        const int buf = kt & 1;
        float4 na, nb;
        if (kt + 1 < NT) {
            na = *(const float4*)(Ag + (kt + 1) * 8);
            nb = *(const float4*)(Bg + (size_t)(kt + 1) * 8 * U_);
        }
        #pragma unroll
        for (int k = 0; k < 8; k++) {
            float4 a0 = *(const float4*)&As[buf][k][tm];
            float4 a1 = *(const float4*)&As[buf][k][tm + 4];
            float4 b0 = *(const float4*)&Bs[buf][k][tn];
            float4 b1 = *(const float4*)&Bs[buf][k][tn + 4];
            float av[8] = {a0.x, a0.y, a0.z, a0.w, a1.x, a1.y, a1.z, a1.w};
            float bv[8] = {b0.x, b0.y, b0.z, b0.w, b1.x, b1.y, b1.z, b1.w};
            #pragma unroll
            for (int i = 0; i < 8; i++)
                #pragma unroll
                for (int j = 0; j < 8; j++) acc[i][j] += av[i] * bv[j];
        }
        if (kt + 1 < NT) {
            const int nbuf = buf ^ 1;
            As[nbuf][acol + 0][arow] = na.x;
            As[nbuf][acol + 1][arow] = na.y;
            As[nbuf][acol + 2][arow] = na.z;
            As[nbuf][acol + 3][arow] = na.w;
            *(float4*)&Bs[nbuf][brow][bcol] = nb;
        }
        __syncthreads();
    }

    #pragma unroll
    for (int i = 0; i < 8; i++) {
        float* Cr = C + (size_t)(m0 + tm + i) * U_ + n0 + tn;
        *(float4*)Cr       = make_float4(acc[i][0], acc[i][1], acc[i][2], acc[i][3]);
        *(float4*)(Cr + 4) = make_float4(acc[i][4], acc[i][5], acc[i][6], acc[i][7]);
    }
}

// ---------------------------------------------------------------------------
// 5) Gather + sigmoid-gated reduce + relu + sent_mask + transpose to [S,B,U]
//    One block per node; thread t = output channel u.
// ---------------------------------------------------------------------------
__device__ __forceinline__ float sigmoidf_(float g) { return 1.f / (1.f + expf(-g)); }

__global__ void gather_kernel(const float* __restrict__ b_in,
                              const float* __restrict__ bg_in,
                              const float* __restrict__ b_out,
                              const float* __restrict__ bg_out,
                              const float* __restrict__ mask_in,
                              const float* __restrict__ mask_out,
                              const float* __restrict__ mask_loop,
                              const float* __restrict__ sent_mask,
                              float* __restrict__ out) {
    const int n = blockIdx.x;
    const int t = threadIdx.x;                 // u
    const int s = n & (S_ - 1);
    const int b = n >> 8;

    __shared__ float sp[33];
    __shared__ int   sidx[33];
    __shared__ int   sl[33];

    if (t < 33) {
        float p; int idx = 0, l = 0;
        if (t < 16) {
            int e = n * DEG_ + t;
            idx = g_ein[e]; l = g_lin[e];
            p = sigmoidf_(g_gin[idx] + bg_in[l]) * mask_in[(size_t)n * DEG_ + t];
        } else if (t < 32) {
            int k = t - 16;
            int e = n * DEG_ + k;
            idx = g_eout[e]; l = g_lout[e];
            p = sigmoidf_(g_gout[idx] + bg_out[l]) * mask_out[(size_t)n * DEG_ + k];
        } else {
            p = sigmoidf_(g_gloop[n]) * mask_loop[n];
        }
        sp[t] = p; sidx[t] = idx; sl[t] = l;
    }
    __syncthreads();

    const float sent = sent_mask[(size_t)s * B_ + b];
    float acc = sp[32] * g_same[(size_t)n * U_ + t];
    #pragma unroll
    for (int k = 0; k < 16; k++) {
        int l = sl[k];
        acc += sp[k] * (g_all_in[((size_t)l * N_ + sidx[k]) * U_ + t] + b_in[l * U_ + t]);
    }
    #pragma unroll
    for (int k = 16; k < 32; k++) {
        int l = sl[k];
        acc += sp[k] * (g_all_out[((size_t)l * N_ + sidx[k]) * U_ + t] + b_out[l * U_ + t]);
    }
    acc = fmaxf(acc, 0.f) * sent;
    out[(size_t)s * B_ * U_ + (size_t)b * U_ + t] = acc;
}

// ---------------------------------------------------------------------------
// Launch
// ---------------------------------------------------------------------------
extern "C" void kernel_launch(void* const* d_in, const int* in_sizes, int n_in,
                              void* d_out, int out_size) {
    const float* src        = (const float*)d_in[0];
    const float* V_in       = (const float*)d_in[1];
    const float* b_in       = (const float*)d_in[2];
    const float* V_in_gate  = (const float*)d_in[3];
    const float* b_in_gate  = (const float*)d_in[4];
    const float* V_out      = (const float*)d_in[5];
    const float* b_out      = (const float*)d_in[6];
    const float* V_out_gate = (const float*)d_in[7];
    const float* b_out_gate = (const float*)d_in[8];
    const float* W_self     = (const float*)d_in[9];
    const float* W_self_g   = (const float*)d_in[10];
    const void*  arc_in     = d_in[11];
    const void*  arc_out    = d_in[12];
    const void*  lab_in     = d_in[13];
    const void*  lab_out    = d_in[14];
    const float* mask_in    = (const float*)d_in[15];
    const float* mask_out   = (const float*)d_in[16];
    const float* mask_loop  = (const float*)d_in[17];
    const float* sent_mask  = (const float*)d_in[18];
    float* out = (float*)d_out;

    prep_x_kernel<<<N_, 256>>>(src);
    prep_edges_kernel<<<E_ / 256, 256>>>(arc_in, lab_in, arc_out, lab_out);
    gates_kernel<<<N_ / 8, 256>>>(V_in_gate, V_out_gate, W_self_g);

    dim3 gg(N_ / 128, U_ / 128, 2 * L_ + 1);   // 64 x 2 x 33
    gemm_kernel<<<gg, 256>>>(V_in, V_out, W_self);

    gather_kernel<<<N_, U_>>>(b_in, b_in_gate, b_out, b_out_gate,
                              mask_in, mask_out, mask_loop, sent_mask, out);
}

// round 7
// speedup vs baseline: 2.2773x; 2.2773x over previous
#include <cuda_runtime.h>
#include <cuda_bf16.h>
#include <cstdint>

// Problem constants
#define B_    32
#define S_    256
#define D_    256
#define U_    256
#define L_    16
#define DEG_  16
#define N_    (B_ * S_)        // 8192
#define E_    (N_ * DEG_)      // 131072
#define KTOT  768              // 3 * 256 (split-bf16 packed K)
#define NMAT  33               // 16 in + 16 out + 1 self

// GEMM tiling (mma.sync path)
#define MTILE   128
#define NTILE   128
#define BK      64                       // bf16 per K-chunk (128 bytes per row)
#define NCHUNK  (KTOT / BK)              // 12
#define STAGE   (MTILE * 128 + NTILE * 128)   // 16KB A + 16KB B = 32768
#define SMEM_TOTAL (2 * STAGE)           // 65536 (dynamic smem)

// ---------------------------------------------------------------------------
// Scratch (device globals: allocation-free rule)
// ---------------------------------------------------------------------------
__device__ float g_x[(size_t)N_ * D_];
__device__ __align__(16) __nv_bfloat16 g_xa[(size_t)N_ * KTOT];          // [N,768] = [hi|hi|lo]
__device__ __align__(16) __nv_bfloat16 g_wb[(size_t)NMAT * U_ * KTOT];   // [33][u][768] = [hi|lo|hi]
__device__ float g_all_in [(size_t)L_ * N_ * U_];
__device__ float g_all_out[(size_t)L_ * N_ * U_];
__device__ float g_same[(size_t)N_ * U_];
__device__ float g_gin[N_], g_gout[N_], g_gloop[N_];
__device__ int   g_ein[E_], g_lin[E_], g_eout[E_], g_lout[E_];

// ---------------------------------------------------------------------------
// PTX helpers (all sm_80+-portable: no tcgen05 anywhere)
// ---------------------------------------------------------------------------
__device__ __forceinline__ uint32_t smem_u32(const void* p) {
    uint32_t a;
    asm("{ .reg .u64 t; cvta.to.shared.u64 t, %1; cvt.u32.u64 %0, t; }" : "=r"(a) : "l"(p));
    return a;
}
__device__ __forceinline__ void cp_async16(uint32_t dst, const void* src) {
    asm volatile("cp.async.cg.shared.global [%0], [%1], 16;" :: "r"(dst), "l"(src) : "memory");
}
#define CP_COMMIT() asm volatile("cp.async.commit_group;" ::: "memory")

__device__ __forceinline__ uint32_t swz128(uint32_t off) {
    return off ^ ((off >> 3) & 0x70);
}
__device__ __forceinline__ void ldmatrix_x4(uint32_t* r, uint32_t addr) {
    asm volatile("ldmatrix.sync.aligned.m8n8.x4.shared.b16 {%0,%1,%2,%3}, [%4];"
                 : "=r"(r[0]), "=r"(r[1]), "=r"(r[2]), "=r"(r[3]) : "r"(addr));
}
__device__ __forceinline__ void ldmatrix_x2(uint32_t* r, uint32_t addr) {
    asm volatile("ldmatrix.sync.aligned.m8n8.x2.shared.b16 {%0,%1}, [%2];"
                 : "=r"(r[0]), "=r"(r[1]) : "r"(addr));
}
__device__ __forceinline__ void mma_bf16(float* c, const uint32_t* a, const uint32_t* b) {
    asm volatile(
        "mma.sync.aligned.m16n8k16.row.col.f32.bf16.bf16.f32 "
        "{%0,%1,%2,%3}, {%4,%5,%6,%7}, {%8,%9}, {%0,%1,%2,%3};"
        : "+f"(c[0]), "+f"(c[1]), "+f"(c[2]), "+f"(c[3])
        : "r"(a[0]), "r"(a[1]), "r"(a[2]), "r"(a[3]), "r"(b[0]), "r"(b[1]));
}

// ---------------------------------------------------------------------------
// 1) x[n,d] = src[s,b,d]; also build split-bf16 packed A' = [hi | hi | lo]
// ---------------------------------------------------------------------------
__global__ void prep_x_kernel(const float* __restrict__ src) {
    int n = blockIdx.x;
    int s = n & (S_ - 1);
    int b = n >> 8;
    int t = threadIdx.x;
    float x = src[(size_t)s * B_ * D_ + (size_t)b * D_ + t];
    g_x[(size_t)n * D_ + t] = x;
    __nv_bfloat16 hi = __float2bfloat16(x);
    __nv_bfloat16 lo = __float2bfloat16(x - __bfloat162float(hi));
    __nv_bfloat16* row = g_xa + (size_t)n * KTOT;
    row[t] = hi; row[256 + t] = hi; row[512 + t] = lo;
}

// ---------------------------------------------------------------------------
// 1b) Transpose + split weights: WB[mat][u][d] = [hi(W[d][u]) | lo | hi]
// ---------------------------------------------------------------------------
__global__ void prep_w_kernel(const float* __restrict__ Vin,
                              const float* __restrict__ Vout,
                              const float* __restrict__ Ws) {
    int z = blockIdx.z;
    const float* W;
    if (z < L_)          W = Vin  + (size_t)z * D_ * U_;
    else if (z < 2 * L_) W = Vout + (size_t)(z - L_) * D_ * U_;
    else                 W = Ws;

    __shared__ float tile[32][33];
    int d0 = blockIdx.y * 32, u0 = blockIdx.x * 32;
    int tx = threadIdx.x, ty = threadIdx.y;
    #pragma unroll
    for (int j = 0; j < 32; j += 8)
        tile[ty + j][tx] = W[(size_t)(d0 + ty + j) * U_ + u0 + tx];
    __syncthreads();
    __nv_bfloat16* base = g_wb + (size_t)z * U_ * KTOT;
    #pragma unroll
    for (int j = 0; j < 32; j += 8) {
        int u = u0 + ty + j, d = d0 + tx;
        float w = tile[tx][ty + j];
        __nv_bfloat16 hi = __float2bfloat16(w);
        __nv_bfloat16 lo = __float2bfloat16(w - __bfloat162float(hi));
        __nv_bfloat16* row = base + (size_t)u * KTOT;
        row[d] = hi; row[256 + d] = lo; row[512 + d] = hi;
    }
}

// ---------------------------------------------------------------------------
// 2) Edge decode (handles int64-or-int32 materialization)
// ---------------------------------------------------------------------------
__device__ __forceinline__ int detect_is64(const int* p) {
    int z = 1;
    #pragma unroll
    for (int i = 1; i < 128; i += 2) z &= (p[i] == 0);
    return z;
}
__global__ void prep_edges_kernel(const void* __restrict__ arc_in,
                                  const void* __restrict__ lab_in,
                                  const void* __restrict__ arc_out,
                                  const void* __restrict__ lab_out) {
    __shared__ int s64;
    if (threadIdx.x == 0) s64 = detect_is64((const int*)arc_in);
    __syncthreads();
    int e = blockIdx.x * blockDim.x + threadIdx.x;
    if (e >= E_) return;
    int bi, si, li, bo, so, lo;
    if (s64) {
        const long long* ai = (const long long*)arc_in;
        const long long* ao = (const long long*)arc_out;
        bi = (int)ai[e];  si = (int)ai[E_ + e];  li = (int)((const long long*)lab_in)[e];
        bo = (int)ao[e];  so = (int)ao[E_ + e];  lo = (int)((const long long*)lab_out)[e];
    } else {
        const int* ai = (const int*)arc_in;
        const int* ao = (const int*)arc_out;
        bi = ai[e];  si = ai[E_ + e];  li = ((const int*)lab_in)[e];
        bo = ao[e];  so = ao[E_ + e];  lo = ((const int*)lab_out)[e];
    }
    g_ein[e]  = bi * S_ + si;  g_lin[e]  = li;
    g_eout[e] = bo * S_ + so;  g_lout[e] = lo;
}

// ---------------------------------------------------------------------------
// 3) Per-node gate dot products (fp32, exact)
// ---------------------------------------------------------------------------
__global__ void gates_kernel(const float* __restrict__ vgin,
                             const float* __restrict__ vgout,
                             const float* __restrict__ wgloop) {
    int gid  = blockIdx.x * blockDim.x + threadIdx.x;
    int warp = gid >> 5;
    int lane = threadIdx.x & 31;
    if (warp >= N_) return;
    const float* xr = g_x + (size_t)warp * D_;
    float a = 0.f, b = 0.f, c = 0.f;
    #pragma unroll
    for (int d = lane; d < D_; d += 32) {
        float xv = xr[d];
        a += xv * vgin[d];
        b += xv * vgout[d];
        c += xv * wgloop[d];
    }
    #pragma unroll
    for (int off = 16; off; off >>= 1) {
        a += __shfl_xor_sync(0xffffffffu, a, off);
        b += __shfl_xor_sync(0xffffffffu, b, off);
        c += __shfl_xor_sync(0xffffffffu, c, off);
    }
    if (lane == 0) { g_gin[warp] = a; g_gout[warp] = b; g_gloop[warp] = c; }
}

// ---------------------------------------------------------------------------
// 4) mma.sync bf16 GEMM: C[mat] = A'(8192x768) @ B'[mat]^T (256x768)
//    CTA 128x128, 8 warps (2m x 4n), warp tile 64x32, BK=64, double-buffered.
// ---------------------------------------------------------------------------
__device__ __forceinline__ void load_stage(uint32_t sbase, int buf, int kt,
                                           const __nv_bfloat16* wrow0, int m0, int t) {
    uint32_t ab = sbase + buf * STAGE;
    uint32_t bb = ab + MTILE * 128;
    #pragma unroll
    for (int r = 0; r < 4; r++) {
        int i = r * 256 + t;                 // 0..1023 : 16B segments of A tile
        int row = i >> 3, seg = i & 7;
        const char* srcA = (const char*)g_xa +
            (((size_t)(m0 + row) * KTOT + (size_t)kt * BK) << 1) + seg * 16;
        cp_async16(ab + swz128(row * 128 + seg * 16), srcA);
    }
    #pragma unroll
    for (int r = 0; r < 4; r++) {
        int i = r * 256 + t;                 // B tile: rows are u-rows of B'
        int row = i >> 3, seg = i & 7;
        const char* srcB = (const char*)wrow0 +
            (((size_t)row * KTOT + (size_t)kt * BK) << 1) + seg * 16;
        cp_async16(bb + swz128(row * 128 + seg * 16), srcB);
    }
}

__global__ void __launch_bounds__(256, 2) gemm_mma_kernel() {
    extern __shared__ char smem[];
    uint32_t sbase = smem_u32(smem);
    const int t = threadIdx.x, wid = t >> 5, lane = t & 31;
    const int wm = wid & 1, wn = wid >> 1;           // 2 x 4 warp grid
    const int mat = blockIdx.z;
    const int m0 = blockIdx.x * MTILE, n0 = blockIdx.y * NTILE;
    const __nv_bfloat16* wrow0 = g_wb + (size_t)mat * U_ * KTOT + (size_t)n0 * KTOT;

    float acc[4][4][4];
    #pragma unroll
    for (int i = 0; i < 4; i++)
        #pragma unroll
        for (int j = 0; j < 4; j++)
            #pragma unroll
            for (int q = 0; q < 4; q++) acc[i][j][q] = 0.f;

    load_stage(sbase, 0, 0, wrow0, m0, t);
    CP_COMMIT();

    // precomputed per-lane fragment addresses (byte offsets within tiles)
    const int a_row = wm * 64 + (lane & 15);         // + mi*16
    const int a_cb  = (lane >> 4) * 16;              // + ks*32
    const int b_row = wn * 32 + (lane & 7);          // + ni*8
    const int b_cb  = ((lane >> 3) & 1) * 16;        // + ks*32

    for (int kt = 0; kt < NCHUNK; kt++) {
        const int buf = kt & 1;
        if (kt + 1 < NCHUNK) {
            load_stage(sbase, buf ^ 1, kt + 1, wrow0, m0, t);
            CP_COMMIT();
            asm volatile("cp.async.wait_group 1;" ::: "memory");
        } else {
            asm volatile("cp.async.wait_group 0;" ::: "memory");
        }
        __syncthreads();

        uint32_t ab = sbase + buf * STAGE;
        uint32_t bb = ab + MTILE * 128;
        #pragma unroll
        for (int ks = 0; ks < 4; ks++) {
            const int kb = ks * 32;
            uint32_t a_frag[4][4], b_frag[4][2];
            #pragma unroll
            for (int mi = 0; mi < 4; mi++)
                ldmatrix_x4(a_frag[mi],
                    ab + swz128((a_row + mi * 16) * 128 + kb + a_cb));
            #pragma unroll
            for (int ni = 0; ni < 4; ni++)
                ldmatrix_x2(b_frag[ni],
                    bb + swz128((b_row + ni * 8) * 128 + kb + b_cb));
            #pragma unroll
            for (int mi = 0; mi < 4; mi++)
                #pragma unroll
                for (int ni = 0; ni < 4; ni++)
                    mma_bf16(acc[mi][ni], a_frag[mi], b_frag[ni]);
        }
        __syncthreads();
    }

    float* C;
    if (mat < L_)            C = g_all_in  + (size_t)mat * N_ * U_;
    else if (mat < 2 * L_)   C = g_all_out + (size_t)(mat - L_) * N_ * U_;
    else                     C = g_same;

    const int r0 = m0 + wm * 64 + (lane >> 2);
    const int c0 = n0 + wn * 32 + (lane & 3) * 2;
    #pragma unroll
    for (int mi = 0; mi < 4; mi++) {
        #pragma unroll
        for (int ni = 0; ni < 4; ni++) {
            float* p0 = C + (size_t)(r0 + mi * 16) * U_ + c0 + ni * 8;
            float* p1 = p0 + 8 * U_;
            *(float2*)p0 = make_float2(acc[mi][ni][0], acc[mi][ni][1]);
            *(float2*)p1 = make_float2(acc[mi][ni][2], acc[mi][ni][3]);
        }
    }
}

// ---------------------------------------------------------------------------
// 5) Gather + sigmoid-gated reduce + relu + sent_mask + transpose to [S,B,U]
// ---------------------------------------------------------------------------
__device__ __forceinline__ float sigmoidf_(float g) { return 1.f / (1.f + expf(-g)); }

__global__ void gather_kernel(const float* __restrict__ b_in,
                              const float* __restrict__ bg_in,
                              const float* __restrict__ b_out,
                              const float* __restrict__ bg_out,
                              const float* __restrict__ mask_in,
                              const float* __restrict__ mask_out,
                              const float* __restrict__ mask_loop,
                              const float* __restrict__ sent_mask,
                              float* __restrict__ out) {
    const int n = blockIdx.x;
    const int t = threadIdx.x;
    const int s = n & (S_ - 1);
    const int b = n >> 8;

    __shared__ float sp[33];
    __shared__ int   sidx[33];
    __shared__ int   sl[33];

    if (t < 33) {
        float p; int idx = 0, l = 0;
        if (t < 16) {
            int e = n * DEG_ + t;
            idx = g_ein[e]; l = g_lin[e];
            p = sigmoidf_(g_gin[idx] + bg_in[l]) * mask_in[(size_t)n * DEG_ + t];
        } else if (t < 32) {
            int k = t - 16;
            int e = n * DEG_ + k;
            idx = g_eout[e]; l = g_lout[e];
            p = sigmoidf_(g_gout[idx] + bg_out[l]) * mask_out[(size_t)n * DEG_ + k];
        } else {
            p = sigmoidf_(g_gloop[n]) * mask_loop[n];
        }
        sp[t] = p; sidx[t] = idx; sl[t] = l;
    }
    __syncthreads();

    const float sent = sent_mask[(size_t)s * B_ + b];
    float acc = sp[32] * g_same[(size_t)n * U_ + t];
    #pragma unroll
    for (int k = 0; k < 16; k++) {
        int l = sl[k];
        acc += sp[k] * (g_all_in[((size_t)l * N_ + sidx[k]) * U_ + t] + b_in[l * U_ + t]);
    }
    #pragma unroll
    for (int k = 16; k < 32; k++) {
        int l = sl[k];
        acc += sp[k] * (g_all_out[((size_t)l * N_ + sidx[k]) * U_ + t] + b_out[l * U_ + t]);
    }
    acc = fmaxf(acc, 0.f) * sent;
    out[(size_t)s * B_ * U_ + (size_t)b * U_ + t] = acc;
}

// ---------------------------------------------------------------------------
// Launch
// ---------------------------------------------------------------------------
extern "C" void kernel_launch(void* const* d_in, const int* in_sizes, int n_in,
                              void* d_out, int out_size) {
    const float* src        = (const float*)d_in[0];
    const float* V_in       = (const float*)d_in[1];
    const float* b_in       = (const float*)d_in[2];
    const float* V_in_gate  = (const float*)d_in[3];
    const float* b_in_gate  = (const float*)d_in[4];
    const float* V_out      = (const float*)d_in[5];
    const float* b_out      = (const float*)d_in[6];
    const float* V_out_gate = (const float*)d_in[7];
    const float* b_out_gate = (const float*)d_in[8];
    const float* W_self     = (const float*)d_in[9];
    const float* W_self_g   = (const float*)d_in[10];
    const void*  arc_in     = d_in[11];
    const void*  arc_out    = d_in[12];
    const void*  lab_in     = d_in[13];
    const void*  lab_out    = d_in[14];
    const float* mask_in    = (const float*)d_in[15];
    const float* mask_out   = (const float*)d_in[16];
    const float* mask_loop  = (const float*)d_in[17];
    const float* sent_mask  = (const float*)d_in[18];
    float* out = (float*)d_out;

    cudaFuncSetAttribute(gemm_mma_kernel,
                         cudaFuncAttributeMaxDynamicSharedMemorySize, SMEM_TOTAL);

    prep_x_kernel<<<N_, 256>>>(src);
    prep_w_kernel<<<dim3(8, 8, NMAT), dim3(32, 8)>>>(V_in, V_out, W_self);
    prep_edges_kernel<<<E_ / 256, 256>>>(arc_in, lab_in, arc_out, lab_out);
    gates_kernel<<<N_ / 8, 256>>>(V_in_gate, V_out_gate, W_self_g);

    gemm_mma_kernel<<<dim3(N_ / MTILE, U_ / NTILE, NMAT), 256, SMEM_TOTAL>>>();

    gather_kernel<<<N_, U_>>>(b_in, b_in_gate, b_out, b_out_gate,
                              mask_in, mask_out, mask_loop, sent_mask, out);
}

// round 8
// speedup vs baseline: 2.8939x; 1.2708x over previous
#include <cuda_runtime.h>
#include <cuda_bf16.h>
#include <cuda_fp16.h>
#include <cstdint>

// Problem constants
#define B_    32
#define S_    256
#define D_    256
#define U_    256
#define L_    16
#define DEG_  16
#define N_    (B_ * S_)        // 8192
#define E_    (N_ * DEG_)      // 131072
#define KA    512              // packed A K: [x_hi | x_lo] fp16
#define KB    256              // stored B K: w_hi fp16 (reused for both A halves)
#define NMAT  33               // 16 in + 16 out + 1 self

// GEMM tiling
#define MTILE   128
#define NTILE   256
#define BK      64                         // fp16 per K-chunk (128B rows)
#define NCHUNK  (KA / BK)                  // 8 A-chunks; B slab = chunk & 3
#define A_STAGE (MTILE * 128)              // 16KB
#define SMEM_B_OFF (2 * A_STAGE)           // 32KB
#define B_SLAB  (NTILE * 128)              // 32KB per 64-k slab
#define SMEM_TOTAL (SMEM_B_OFF + 4 * B_SLAB)   // 32KB + 128KB = 163840

// ---------------------------------------------------------------------------
// Scratch (device globals: allocation-free rule)
// ---------------------------------------------------------------------------
__device__ float g_x[(size_t)N_ * D_];
__device__ __align__(16) __half g_xa[(size_t)N_ * KA];            // [N,512] = [hi|lo]
__device__ __align__(16) __half g_wb[(size_t)NMAT * U_ * KB];     // [33][u][256] = w_hi^T
__device__ float g_all_in [(size_t)L_ * N_ * U_];
__device__ float g_all_out[(size_t)L_ * N_ * U_];
__device__ float g_same[(size_t)N_ * U_];
__device__ float g_gin[N_], g_gout[N_], g_gloop[N_];
__device__ int   g_ein[E_], g_lin[E_], g_eout[E_], g_lout[E_];

// ---------------------------------------------------------------------------
// PTX helpers (sm_80+-portable only)
// ---------------------------------------------------------------------------
__device__ __forceinline__ uint32_t smem_u32(const void* p) {
    uint32_t a;
    asm("{ .reg .u64 t; cvta.to.shared.u64 t, %1; cvt.u32.u64 %0, t; }" : "=r"(a) : "l"(p));
    return a;
}
__device__ __forceinline__ void cp_async16(uint32_t dst, const void* src) {
    asm volatile("cp.async.cg.shared.global [%0], [%1], 16;" :: "r"(dst), "l"(src) : "memory");
}
#define CP_COMMIT() asm volatile("cp.async.commit_group;" ::: "memory")

__device__ __forceinline__ uint32_t swz128(uint32_t off) {
    return off ^ ((off >> 3) & 0x70);
}
__device__ __forceinline__ void ldmatrix_x4(uint32_t* r, uint32_t addr) {
    asm volatile("ldmatrix.sync.aligned.m8n8.x4.shared.b16 {%0,%1,%2,%3}, [%4];"
                 : "=r"(r[0]), "=r"(r[1]), "=r"(r[2]), "=r"(r[3]) : "r"(addr));
}
__device__ __forceinline__ void ldmatrix_x2(uint32_t* r, uint32_t addr) {
    asm volatile("ldmatrix.sync.aligned.m8n8.x2.shared.b16 {%0,%1}, [%2];"
                 : "=r"(r[0]), "=r"(r[1]) : "r"(addr));
}
__device__ __forceinline__ void mma_f16(float* c, const uint32_t* a, const uint32_t* b) {
    asm volatile(
        "mma.sync.aligned.m16n8k16.row.col.f32.f16.f16.f32 "
        "{%0,%1,%2,%3}, {%4,%5,%6,%7}, {%8,%9}, {%0,%1,%2,%3};"
        : "+f"(c[0]), "+f"(c[1]), "+f"(c[2]), "+f"(c[3])
        : "r"(a[0]), "r"(a[1]), "r"(a[2]), "r"(a[3]), "r"(b[0]), "r"(b[1]));
}

// ---------------------------------------------------------------------------
// 1) x[n,d] = src[s,b,d]; packed A' = [fp16 hi | fp16 lo]
// ---------------------------------------------------------------------------
__global__ void prep_x_kernel(const float* __restrict__ src) {
    int n = blockIdx.x;
    int s = n & (S_ - 1);
    int b = n >> 8;
    int t = threadIdx.x;
    float x = src[(size_t)s * B_ * D_ + (size_t)b * D_ + t];
    g_x[(size_t)n * D_ + t] = x;
    __half hi = __float2half(x);
    __half lo = __float2half(x - __half2float(hi));
    __half* row = g_xa + (size_t)n * KA;
    row[t] = hi; row[256 + t] = lo;
}

// ---------------------------------------------------------------------------
// 1b) Transpose weights to [u][d], fp16
// ---------------------------------------------------------------------------
__global__ void prep_w_kernel(const float* __restrict__ Vin,
                              const float* __restrict__ Vout,
                              const float* __restrict__ Ws) {
    int z = blockIdx.z;
    const float* W;
    if (z < L_)          W = Vin  + (size_t)z * D_ * U_;
    else if (z < 2 * L_) W = Vout + (size_t)(z - L_) * D_ * U_;
    else                 W = Ws;

    __shared__ float tile[32][33];
    int d0 = blockIdx.y * 32, u0 = blockIdx.x * 32;
    int tx = threadIdx.x, ty = threadIdx.y;
    #pragma unroll
    for (int j = 0; j < 32; j += 8)
        tile[ty + j][tx] = W[(size_t)(d0 + ty + j) * U_ + u0 + tx];
    __syncthreads();
    __half* base = g_wb + (size_t)z * U_ * KB;
    #pragma unroll
    for (int j = 0; j < 32; j += 8) {
        int u = u0 + ty + j, d = d0 + tx;
        base[(size_t)u * KB + d] = __float2half(tile[tx][ty + j]);
    }
}

// ---------------------------------------------------------------------------
// 2) Edge decode (handles int64-or-int32 materialization)
// ---------------------------------------------------------------------------
__device__ __forceinline__ int detect_is64(const int* p) {
    int z = 1;
    #pragma unroll
    for (int i = 1; i < 128; i += 2) z &= (p[i] == 0);
    return z;
}
__global__ void prep_edges_kernel(const void* __restrict__ arc_in,
                                  const void* __restrict__ lab_in,
                                  const void* __restrict__ arc_out,
                                  const void* __restrict__ lab_out) {
    __shared__ int s64;
    if (threadIdx.x == 0) s64 = detect_is64((const int*)arc_in);
    __syncthreads();
    int e = blockIdx.x * blockDim.x + threadIdx.x;
    if (e >= E_) return;
    int bi, si, li, bo, so, lo;
    if (s64) {
        const long long* ai = (const long long*)arc_in;
        const long long* ao = (const long long*)arc_out;
        bi = (int)ai[e];  si = (int)ai[E_ + e];  li = (int)((const long long*)lab_in)[e];
        bo = (int)ao[e];  so = (int)ao[E_ + e];  lo = (int)((const long long*)lab_out)[e];
    } else {
        const int* ai = (const int*)arc_in;
        const int* ao = (const int*)arc_out;
        bi = ai[e];  si = ai[E_ + e];  li = ((const int*)lab_in)[e];
        bo = ao[e];  so = ao[E_ + e];  lo = ((const int*)lab_out)[e];
    }
    g_ein[e]  = bi * S_ + si;  g_lin[e]  = li;
    g_eout[e] = bo * S_ + so;  g_lout[e] = lo;
}

// ---------------------------------------------------------------------------
// 3) Per-node gate dot products (fp32, exact)
// ---------------------------------------------------------------------------
__global__ void gates_kernel(const float* __restrict__ vgin,
                             const float* __restrict__ vgout,
                             const float* __restrict__ wgloop) {
    int gid  = blockIdx.x * blockDim.x + threadIdx.x;
    int warp = gid >> 5;
    int lane = threadIdx.x & 31;
    if (warp >= N_) return;
    const float* xr = g_x + (size_t)warp * D_;
    float a = 0.f, b = 0.f, c = 0.f;
    #pragma unroll
    for (int d = lane; d < D_; d += 32) {
        float xv = xr[d];
        a += xv * vgin[d];
        b += xv * vgout[d];
        c += xv * wgloop[d];
    }
    #pragma unroll
    for (int off = 16; off; off >>= 1) {
        a += __shfl_xor_sync(0xffffffffu, a, off);
        b += __shfl_xor_sync(0xffffffffu, b, off);
        c += __shfl_xor_sync(0xffffffffu, c, off);
    }
    if (lane == 0) { g_gin[warp] = a; g_gout[warp] = b; g_gloop[warp] = c; }
}

// ---------------------------------------------------------------------------
// 4) mma.sync fp16 GEMM: C[mat] = A'(8192x512) @ whi[mat]^T (dup-K)
//    CTA 128x256, 8 warps (2m x 4n), warp tile 64x64.
//    B (128KB) resident in smem; A double-buffered 64-k chunks.
// ---------------------------------------------------------------------------
__device__ __forceinline__ void load_a_chunk(uint32_t sbase, int buf, int kt,
                                             int m0, int t) {
    uint32_t ab = sbase + buf * A_STAGE;
    #pragma unroll
    for (int r = 0; r < 4; r++) {
        int i = r * 256 + t;                  // 1024 16B segments
        int row = i >> 3, seg = i & 7;
        int kk = (kt * BK) & (KB - 1);        // A chunk kt reads w-k range kt*64 mod 256
        (void)kk;
        const char* src = (const char*)g_xa +
            (((size_t)(m0 + row) * KA + (size_t)kt * BK) << 1) + seg * 16;
        cp_async16(ab + swz128(row * 128 + seg * 16), src);
    }
}

__global__ void __launch_bounds__(256, 1) gemm_mma_kernel() {
    extern __shared__ char smem[];
    uint32_t sbase = smem_u32(smem);
    const int t = threadIdx.x, wid = t >> 5, lane = t & 31;
    const int wm = wid & 1, wn = wid >> 1;            // 2m x 4n warp grid
    const int mat = blockIdx.y;
    const int m0 = blockIdx.x * MTILE;
    const __half* wrow0 = g_wb + (size_t)mat * U_ * KB;

    // B resident: 4 slabs of 64 k, 256 u-rows each
    #pragma unroll
    for (int s = 0; s < 4; s++) {
        uint32_t bb = sbase + SMEM_B_OFF + s * B_SLAB;
        #pragma unroll
        for (int r = 0; r < 8; r++) {
            int i = r * 256 + t;              // 2048 16B segments per slab
            int row = i >> 3, seg = i & 7;
            const char* src = (const char*)wrow0 +
                (((size_t)row * KB + (size_t)s * BK) << 1) + seg * 16;
            cp_async16(bb + swz128(row * 128 + seg * 16), src);
        }
    }
    load_a_chunk(sbase, 0, 0, m0, t);
    CP_COMMIT();                               // group: all B + A0

    float acc[4][8][4];
    #pragma unroll
    for (int i = 0; i < 4; i++)
        #pragma unroll
        for (int j = 0; j < 8; j++)
            #pragma unroll
            for (int q = 0; q < 4; q++) acc[i][j][q] = 0.f;

    const int a_row = wm * 64 + (lane & 15);
    const int a_cb  = (lane >> 4) * 16;
    const int b_row = wn * 64 + (lane & 7);
    const int b_cb  = ((lane >> 3) & 1) * 16;

    for (int kt = 0; kt < NCHUNK; kt++) {
        const int buf = kt & 1;
        if (kt + 1 < NCHUNK) {
            load_a_chunk(sbase, buf ^ 1, kt + 1, m0, t);
            CP_COMMIT();
            asm volatile("cp.async.wait_group 1;" ::: "memory");
        } else {
            asm volatile("cp.async.wait_group 0;" ::: "memory");
        }
        __syncthreads();

        uint32_t ab = sbase + buf * A_STAGE;
        uint32_t bb = sbase + SMEM_B_OFF + (kt & 3) * B_SLAB;
        #pragma unroll
        for (int ks = 0; ks < 4; ks++) {
            const int kb = ks * 32;
            uint32_t a_frag[4][4], b_frag[8][2];
            #pragma unroll
            for (int mi = 0; mi < 4; mi++)
                ldmatrix_x4(a_frag[mi],
                    ab + swz128((a_row + mi * 16) * 128 + kb + a_cb));
            #pragma unroll
            for (int ni = 0; ni < 8; ni++)
                ldmatrix_x2(b_frag[ni],
                    bb + swz128((b_row + ni * 8) * 128 + kb + b_cb));
            #pragma unroll
            for (int mi = 0; mi < 4; mi++)
                #pragma unroll
                for (int ni = 0; ni < 8; ni++)
                    mma_f16(acc[mi][ni], a_frag[mi], b_frag[ni]);
        }
        __syncthreads();
    }

    float* C;
    if (mat < L_)            C = g_all_in  + (size_t)mat * N_ * U_;
    else if (mat < 2 * L_)   C = g_all_out + (size_t)(mat - L_) * N_ * U_;
    else                     C = g_same;

    const int r0 = m0 + wm * 64 + (lane >> 2);
    const int c0 = wn * 64 + (lane & 3) * 2;
    #pragma unroll
    for (int mi = 0; mi < 4; mi++) {
        #pragma unroll
        for (int ni = 0; ni < 8; ni++) {
            float* p0 = C + (size_t)(r0 + mi * 16) * U_ + c0 + ni * 8;
            float* p1 = p0 + 8 * U_;
            *(float2*)p0 = make_float2(acc[mi][ni][0], acc[mi][ni][1]);
            *(float2*)p1 = make_float2(acc[mi][ni][2], acc[mi][ni][3]);
        }
    }
}

// ---------------------------------------------------------------------------
// 5) Gather + sigmoid-gated reduce + relu + sent_mask + transpose to [S,B,U]
// ---------------------------------------------------------------------------
__device__ __forceinline__ float sigmoidf_(float g) { return 1.f / (1.f + expf(-g)); }

__global__ void gather_kernel(const float* __restrict__ b_in,
                              const float* __restrict__ bg_in,
                              const float* __restrict__ b_out,
                              const float* __restrict__ bg_out,
                              const float* __restrict__ mask_in,
                              const float* __restrict__ mask_out,
                              const float* __restrict__ mask_loop,
                              const float* __restrict__ sent_mask,
                              float* __restrict__ out) {
    const int n = blockIdx.x;
    const int t = threadIdx.x;
    const int s = n & (S_ - 1);
    const int b = n >> 8;

    __shared__ float sp[33];
    __shared__ int   sidx[33];
    __shared__ int   sl[33];

    if (t < 33) {
        float p; int idx = 0, l = 0;
        if (t < 16) {
            int e = n * DEG_ + t;
            idx = g_ein[e]; l = g_lin[e];
            p = sigmoidf_(g_gin[idx] + bg_in[l]) * mask_in[(size_t)n * DEG_ + t];
        } else if (t < 32) {
            int k = t - 16;
            int e = n * DEG_ + k;
            idx = g_eout[e]; l = g_lout[e];
            p = sigmoidf_(g_gout[idx] + bg_out[l]) * mask_out[(size_t)n * DEG_ + k];
        } else {
            p = sigmoidf_(g_gloop[n]) * mask_loop[n];
        }
        sp[t] = p; sidx[t] = idx; sl[t] = l;
    }
    __syncthreads();

    const float sent = sent_mask[(size_t)s * B_ + b];
    float acc = sp[32] * g_same[(size_t)n * U_ + t];
    #pragma unroll
    for (int k = 0; k < 16; k++) {
        int l = sl[k];
        acc += sp[k] * (g_all_in[((size_t)l * N_ + sidx[k]) * U_ + t] + b_in[l * U_ + t]);
    }
    #pragma unroll
    for (int k = 16; k < 32; k++) {
        int l = sl[k];
        acc += sp[k] * (g_all_out[((size_t)l * N_ + sidx[k]) * U_ + t] + b_out[l * U_ + t]);
    }
    acc = fmaxf(acc, 0.f) * sent;
    out[(size_t)s * B_ * U_ + (size_t)b * U_ + t] = acc;
}

// ---------------------------------------------------------------------------
// Launch
// ---------------------------------------------------------------------------
extern "C" void kernel_launch(void* const* d_in, const int* in_sizes, int n_in,
                              void* d_out, int out_size) {
    const float* src        = (const float*)d_in[0];
    const float* V_in       = (const float*)d_in[1];
    const float* b_in       = (const float*)d_in[2];
    const float* V_in_gate  = (const float*)d_in[3];
    const float* b_in_gate  = (const float*)d_in[4];
    const float* V_out      = (const float*)d_in[5];
    const float* b_out      = (const float*)d_in[6];
    const float* V_out_gate = (const float*)d_in[7];
    const float* b_out_gate = (const float*)d_in[8];
    const float* W_self     = (const float*)d_in[9];
    const float* W_self_g   = (const float*)d_in[10];
    const void*  arc_in     = d_in[11];
    const void*  arc_out    = d_in[12];
    const void*  lab_in     = d_in[13];
    const void*  lab_out    = d_in[14];
    const float* mask_in    = (const float*)d_in[15];
    const float* mask_out   = (const float*)d_in[16];
    const float* mask_loop  = (const float*)d_in[17];
    const float* sent_mask  = (const float*)d_in[18];
    float* out = (float*)d_out;

    cudaFuncSetAttribute(gemm_mma_kernel,
                         cudaFuncAttributeMaxDynamicSharedMemorySize, SMEM_TOTAL);

    prep_x_kernel<<<N_, 256>>>(src);
    prep_w_kernel<<<dim3(8, 8, NMAT), dim3(32, 8)>>>(V_in, V_out, W_self);
    prep_edges_kernel<<<E_ / 256, 256>>>(arc_in, lab_in, arc_out, lab_out);
    gates_kernel<<<N_ / 8, 256>>>(V_in_gate, V_out_gate, W_self_g);

    gemm_mma_kernel<<<dim3(N_ / MTILE, NMAT), 256, SMEM_TOTAL>>>();

    gather_kernel<<<N_, U_>>>(b_in, b_in_gate, b_out, b_out_gate,
                              mask_in, mask_out, mask_loop, sent_mask, out);
}

// round 9
// speedup vs baseline: 3.7634x; 1.3005x over previous
#include <cuda_runtime.h>
#include <cuda_bf16.h>
#include <cuda_fp16.h>
#include <cstdint>

// Problem constants
#define B_    32
#define S_    256
#define D_    256
#define U_    256
#define L_    16
#define DEG_  16
#define N_    (B_ * S_)        // 8192
#define E_    (N_ * DEG_)      // 131072
#define KA    256              // fp16 x (single term)
#define KB    256              // fp16 w^T
#define NMAT  33               // 16 in + 16 out + 1 self

// GEMM tiling
#define MTILE   128
#define NTILE   256
#define BK      64                         // fp16 per K-chunk (128B rows)
#define NCHUNK  (KA / BK)                  // 4
#define A_STAGE (MTILE * 128)              // 16KB
#define SMEM_B_OFF (2 * A_STAGE)           // 32KB
#define B_SLAB  (NTILE * 128)              // 32KB per 64-k slab
#define SMEM_TOTAL (SMEM_B_OFF + 4 * B_SLAB)   // 32KB + 128KB = 163840

// ---------------------------------------------------------------------------
// Scratch (device globals: allocation-free rule)
// ---------------------------------------------------------------------------
__device__ float g_x[(size_t)N_ * D_];
__device__ __align__(16) __half g_xa[(size_t)N_ * KA];            // [N,256] fp16 x
__device__ __align__(16) __half g_wb[(size_t)NMAT * U_ * KB];     // [33][u][256] fp16 w^T
__device__ float g_all_in [(size_t)L_ * N_ * U_];
__device__ float g_all_out[(size_t)L_ * N_ * U_];
__device__ float g_same[(size_t)N_ * U_];
__device__ float g_gin[N_], g_gout[N_], g_gloop[N_];
__device__ int   g_ein[E_], g_lin[E_], g_eout[E_], g_lout[E_];

// ---------------------------------------------------------------------------
// PTX helpers (sm_80+-portable only)
// ---------------------------------------------------------------------------
__device__ __forceinline__ uint32_t smem_u32(const void* p) {
    uint32_t a;
    asm("{ .reg .u64 t; cvta.to.shared.u64 t, %1; cvt.u32.u64 %0, t; }" : "=r"(a) : "l"(p));
    return a;
}
__device__ __forceinline__ void cp_async16(uint32_t dst, const void* src) {
    asm volatile("cp.async.cg.shared.global [%0], [%1], 16;" :: "r"(dst), "l"(src) : "memory");
}
#define CP_COMMIT() asm volatile("cp.async.commit_group;" ::: "memory")

__device__ __forceinline__ uint32_t swz128(uint32_t off) {
    return off ^ ((off >> 3) & 0x70);
}
__device__ __forceinline__ void ldmatrix_x4(uint32_t* r, uint32_t addr) {
    asm volatile("ldmatrix.sync.aligned.m8n8.x4.shared.b16 {%0,%1,%2,%3}, [%4];"
                 : "=r"(r[0]), "=r"(r[1]), "=r"(r[2]), "=r"(r[3]) : "r"(addr));
}
__device__ __forceinline__ void ldmatrix_x2(uint32_t* r, uint32_t addr) {
    asm volatile("ldmatrix.sync.aligned.m8n8.x2.shared.b16 {%0,%1}, [%2];"
                 : "=r"(r[0]), "=r"(r[1]) : "r"(addr));
}
__device__ __forceinline__ void mma_f16(float* c, const uint32_t* a, const uint32_t* b) {
    asm volatile(
        "mma.sync.aligned.m16n8k16.row.col.f32.f16.f16.f32 "
        "{%0,%1,%2,%3}, {%4,%5,%6,%7}, {%8,%9}, {%0,%1,%2,%3};"
        : "+f"(c[0]), "+f"(c[1]), "+f"(c[2]), "+f"(c[3])
        : "r"(a[0]), "r"(a[1]), "r"(a[2]), "r"(a[3]), "r"(b[0]), "r"(b[1]));
}

// ---------------------------------------------------------------------------
// 1) x[n,d] = src[s,b,d]; fp16 copy for MMA A operand
// ---------------------------------------------------------------------------
__global__ void prep_x_kernel(const float* __restrict__ src) {
    int n = blockIdx.x;
    int s = n & (S_ - 1);
    int b = n >> 8;
    int t = threadIdx.x;
    float x = src[(size_t)s * B_ * D_ + (size_t)b * D_ + t];
    g_x[(size_t)n * D_ + t] = x;
    g_xa[(size_t)n * KA + t] = __float2half(x);
}

// ---------------------------------------------------------------------------
// 1b) Transpose weights to [u][d], fp16
// ---------------------------------------------------------------------------
__global__ void prep_w_kernel(const float* __restrict__ Vin,
                              const float* __restrict__ Vout,
                              const float* __restrict__ Ws) {
    int z = blockIdx.z;
    const float* W;
    if (z < L_)          W = Vin  + (size_t)z * D_ * U_;
    else if (z < 2 * L_) W = Vout + (size_t)(z - L_) * D_ * U_;
    else                 W = Ws;

    __shared__ float tile[32][33];
    int d0 = blockIdx.y * 32, u0 = blockIdx.x * 32;
    int tx = threadIdx.x, ty = threadIdx.y;
    #pragma unroll
    for (int j = 0; j < 32; j += 8)
        tile[ty + j][tx] = W[(size_t)(d0 + ty + j) * U_ + u0 + tx];
    __syncthreads();
    __half* base = g_wb + (size_t)z * U_ * KB;
    #pragma unroll
    for (int j = 0; j < 32; j += 8) {
        int u = u0 + ty + j, d = d0 + tx;
        base[(size_t)u * KB + d] = __float2half(tile[tx][ty + j]);
    }
}

// ---------------------------------------------------------------------------
// 2) Edge decode (handles int64-or-int32 materialization)
// ---------------------------------------------------------------------------
__device__ __forceinline__ int detect_is64(const int* p) {
    int z = 1;
    #pragma unroll
    for (int i = 1; i < 128; i += 2) z &= (p[i] == 0);
    return z;
}
__global__ void prep_edges_kernel(const void* __restrict__ arc_in,
                                  const void* __restrict__ lab_in,
                                  const void* __restrict__ arc_out,
                                  const void* __restrict__ lab_out) {
    __shared__ int s64;
    if (threadIdx.x == 0) s64 = detect_is64((const int*)arc_in);
    __syncthreads();
    int e = blockIdx.x * blockDim.x + threadIdx.x;
    if (e >= E_) return;
    int bi, si, li, bo, so, lo;
    if (s64) {
        const long long* ai = (const long long*)arc_in;
        const long long* ao = (const long long*)arc_out;
        bi = (int)ai[e];  si = (int)ai[E_ + e];  li = (int)((const long long*)lab_in)[e];
        bo = (int)ao[e];  so = (int)ao[E_ + e];  lo = (int)((const long long*)lab_out)[e];
    } else {
        const int* ai = (const int*)arc_in;
        const int* ao = (const int*)arc_out;
        bi = ai[e];  si = ai[E_ + e];  li = ((const int*)lab_in)[e];
        bo = ao[e];  so = ao[E_ + e];  lo = ((const int*)lab_out)[e];
    }
    g_ein[e]  = bi * S_ + si;  g_lin[e]  = li;
    g_eout[e] = bo * S_ + so;  g_lout[e] = lo;
}

// ---------------------------------------------------------------------------
// 3) Per-node gate dot products (fp32, exact)
// ---------------------------------------------------------------------------
__global__ void gates_kernel(const float* __restrict__ vgin,
                             const float* __restrict__ vgout,
                             const float* __restrict__ wgloop) {
    int gid  = blockIdx.x * blockDim.x + threadIdx.x;
    int warp = gid >> 5;
    int lane = threadIdx.x & 31;
    if (warp >= N_) return;
    const float* xr = g_x + (size_t)warp * D_;
    float a = 0.f, b = 0.f, c = 0.f;
    #pragma unroll
    for (int d = lane; d < D_; d += 32) {
        float xv = xr[d];
        a += xv * vgin[d];
        b += xv * vgout[d];
        c += xv * wgloop[d];
    }
    #pragma unroll
    for (int off = 16; off; off >>= 1) {
        a += __shfl_xor_sync(0xffffffffu, a, off);
        b += __shfl_xor_sync(0xffffffffu, b, off);
        c += __shfl_xor_sync(0xffffffffu, c, off);
    }
    if (lane == 0) { g_gin[warp] = a; g_gout[warp] = b; g_gloop[warp] = c; }
}

// ---------------------------------------------------------------------------
// 4) mma.sync fp16 GEMM: C[mat] = x16(8192x256) @ w16[mat]^T
//    CTA 128x256, 8 warps (2m x 4n), warp tile 64x64.
//    B (128KB) resident in smem; A double-buffered 64-k chunks.
// ---------------------------------------------------------------------------
__device__ __forceinline__ void load_a_chunk(uint32_t sbase, int buf, int kt,
                                             int m0, int t) {
    uint32_t ab = sbase + buf * A_STAGE;
    #pragma unroll
    for (int r = 0; r < 4; r++) {
        int i = r * 256 + t;                  // 1024 16B segments
        int row = i >> 3, seg = i & 7;
        const char* src = (const char*)g_xa +
            (((size_t)(m0 + row) * KA + (size_t)kt * BK) << 1) + seg * 16;
        cp_async16(ab + swz128(row * 128 + seg * 16), src);
    }
}

__global__ void __launch_bounds__(256, 1) gemm_mma_kernel() {
    extern __shared__ char smem[];
    uint32_t sbase = smem_u32(smem);
    const int t = threadIdx.x, wid = t >> 5, lane = t & 31;
    const int wm = wid & 1, wn = wid >> 1;            // 2m x 4n warp grid
    const int mat = blockIdx.y;
    const int m0 = blockIdx.x * MTILE;
    const __half* wrow0 = g_wb + (size_t)mat * U_ * KB;

    // B resident: 4 slabs of 64 k, 256 u-rows each
    #pragma unroll
    for (int s = 0; s < 4; s++) {
        uint32_t bb = sbase + SMEM_B_OFF + s * B_SLAB;
        #pragma unroll
        for (int r = 0; r < 8; r++) {
            int i = r * 256 + t;              // 2048 16B segments per slab
            int row = i >> 3, seg = i & 7;
            const char* src = (const char*)wrow0 +
                (((size_t)row * KB + (size_t)s * BK) << 1) + seg * 16;
            cp_async16(bb + swz128(row * 128 + seg * 16), src);
        }
    }
    load_a_chunk(sbase, 0, 0, m0, t);
    CP_COMMIT();                               // group: all B + A0

    float acc[4][8][4];
    #pragma unroll
    for (int i = 0; i < 4; i++)
        #pragma unroll
        for (int j = 0; j < 8; j++)
            #pragma unroll
            for (int q = 0; q < 4; q++) acc[i][j][q] = 0.f;

    const int a_row = wm * 64 + (lane & 15);
    const int a_cb  = (lane >> 4) * 16;
    const int b_row = wn * 64 + (lane & 7);
    const int b_cb  = ((lane >> 3) & 1) * 16;

    for (int kt = 0; kt < NCHUNK; kt++) {
        const int buf = kt & 1;
        if (kt + 1 < NCHUNK) {
            load_a_chunk(sbase, buf ^ 1, kt + 1, m0, t);
            CP_COMMIT();
            asm volatile("cp.async.wait_group 1;" ::: "memory");
        } else {
            asm volatile("cp.async.wait_group 0;" ::: "memory");
        }
        __syncthreads();

        uint32_t ab = sbase + buf * A_STAGE;
        uint32_t bb = sbase + SMEM_B_OFF + kt * B_SLAB;   // chunk kt <-> slab kt
        #pragma unroll
        for (int ks = 0; ks < 4; ks++) {
            const int kb = ks * 32;
            uint32_t a_frag[4][4], b_frag[8][2];
            #pragma unroll
            for (int mi = 0; mi < 4; mi++)
                ldmatrix_x4(a_frag[mi],
                    ab + swz128((a_row + mi * 16) * 128 + kb + a_cb));
            #pragma unroll
            for (int ni = 0; ni < 8; ni++)
                ldmatrix_x2(b_frag[ni],
                    bb + swz128((b_row + ni * 8) * 128 + kb + b_cb));
            #pragma unroll
            for (int mi = 0; mi < 4; mi++)
                #pragma unroll
                for (int ni = 0; ni < 8; ni++)
                    mma_f16(acc[mi][ni], a_frag[mi], b_frag[ni]);
        }
        __syncthreads();
    }

    float* C;
    if (mat < L_)            C = g_all_in  + (size_t)mat * N_ * U_;
    else if (mat < 2 * L_)   C = g_all_out + (size_t)(mat - L_) * N_ * U_;
    else                     C = g_same;

    const int r0 = m0 + wm * 64 + (lane >> 2);
    const int c0 = wn * 64 + (lane & 3) * 2;
    #pragma unroll
    for (int mi = 0; mi < 4; mi++) {
        #pragma unroll
        for (int ni = 0; ni < 8; ni++) {
            float* p0 = C + (size_t)(r0 + mi * 16) * U_ + c0 + ni * 8;
            float* p1 = p0 + 8 * U_;
            *(float2*)p0 = make_float2(acc[mi][ni][0], acc[mi][ni][1]);
            *(float2*)p1 = make_float2(acc[mi][ni][2], acc[mi][ni][3]);
        }
    }
}

// ---------------------------------------------------------------------------
// 5) Gather + sigmoid-gated reduce + relu + sent_mask + transpose to [S,B,U]
// ---------------------------------------------------------------------------
__device__ __forceinline__ float sigmoidf_(float g) { return 1.f / (1.f + expf(-g)); }

__global__ void gather_kernel(const float* __restrict__ b_in,
                              const float* __restrict__ bg_in,
                              const float* __restrict__ b_out,
                              const float* __restrict__ bg_out,
                              const float* __restrict__ mask_in,
                              const float* __restrict__ mask_out,
                              const float* __restrict__ mask_loop,
                              const float* __restrict__ sent_mask,
                              float* __restrict__ out) {
    const int n = blockIdx.x;
    const int t = threadIdx.x;
    const int s = n & (S_ - 1);
    const int b = n >> 8;

    __shared__ float sp[33];
    __shared__ int   sidx[33];
    __shared__ int   sl[33];

    if (t < 33) {
        float p; int idx = 0, l = 0;
        if (t < 16) {
            int e = n * DEG_ + t;
            idx = g_ein[e]; l = g_lin[e];
            p = sigmoidf_(g_gin[idx] + bg_in[l]) * mask_in[(size_t)n * DEG_ + t];
        } else if (t < 32) {
            int k = t - 16;
            int e = n * DEG_ + k;
            idx = g_eout[e]; l = g_lout[e];
            p = sigmoidf_(g_gout[idx] + bg_out[l]) * mask_out[(size_t)n * DEG_ + k];
        } else {
            p = sigmoidf_(g_gloop[n]) * mask_loop[n];
        }
        sp[t] = p; sidx[t] = idx; sl[t] = l;
    }
    __syncthreads();

    const float sent = sent_mask[(size_t)s * B_ + b];
    float acc = sp[32] * g_same[(size_t)n * U_ + t];
    #pragma unroll
    for (int k = 0; k < 16; k++) {
        int l = sl[k];
        acc += sp[k] * (g_all_in[((size_t)l * N_ + sidx[k]) * U_ + t] + b_in[l * U_ + t]);
    }
    #pragma unroll
    for (int k = 16; k < 32; k++) {
        int l = sl[k];
        acc += sp[k] * (g_all_out[((size_t)l * N_ + sidx[k]) * U_ + t] + b_out[l * U_ + t]);
    }
    acc = fmaxf(acc, 0.f) * sent;
    out[(size_t)s * B_ * U_ + (size_t)b * U_ + t] = acc;
}

// ---------------------------------------------------------------------------
// Launch
// ---------------------------------------------------------------------------
extern "C" void kernel_launch(void* const* d_in, const int* in_sizes, int n_in,
                              void* d_out, int out_size) {
    const float* src        = (const float*)d_in[0];
    const float* V_in       = (const float*)d_in[1];
    const float* b_in       = (const float*)d_in[2];
    const float* V_in_gate  = (const float*)d_in[3];
    const float* b_in_gate  = (const float*)d_in[4];
    const float* V_out      = (const float*)d_in[5];
    const float* b_out      = (const float*)d_in[6];
    const float* V_out_gate = (const float*)d_in[7];
    const float* b_out_gate = (const float*)d_in[8];
    const float* W_self     = (const float*)d_in[9];
    const float* W_self_g   = (const float*)d_in[10];
    const void*  arc_in     = d_in[11];
    const void*  arc_out    = d_in[12];
    const void*  lab_in     = d_in[13];
    const void*  lab_out    = d_in[14];
    const float* mask_in    = (const float*)d_in[15];
    const float* mask_out   = (const float*)d_in[16];
    const float* mask_loop  = (const float*)d_in[17];
    const float* sent_mask  = (const float*)d_in[18];
    float* out = (float*)d_out;

    cudaFuncSetAttribute(gemm_mma_kernel,
                         cudaFuncAttributeMaxDynamicSharedMemorySize, SMEM_TOTAL);

    prep_x_kernel<<<N_, 256>>>(src);
    prep_w_kernel<<<dim3(8, 8, NMAT), dim3(32, 8)>>>(V_in, V_out, W_self);
    prep_edges_kernel<<<E_ / 256, 256>>>(arc_in, lab_in, arc_out, lab_out);
    gates_kernel<<<N_ / 8, 256>>>(V_in_gate, V_out_gate, W_self_g);

    gemm_mma_kernel<<<dim3(N_ / MTILE, NMAT), 256, SMEM_TOTAL>>>();

    gather_kernel<<<N_, U_>>>(b_in, b_in_gate, b_out, b_out_gate,
                              mask_in, mask_out, mask_loop, sent_mask, out);
}

// round 11
// speedup vs baseline: 3.8398x; 1.0203x over previous
#include <cuda_runtime.h>
#include <cuda_bf16.h>
#include <cuda_fp16.h>
#include <cstdint>

// Problem constants
#define B_    32
#define S_    256
#define D_    256
#define U_    256
#define L_    16
#define DEG_  16
#define N_    (B_ * S_)        // 8192
#define E_    (N_ * DEG_)      // 131072
#define KA    256              // fp16 x
#define KB    256              // fp16 w^T
#define NMAT  33               // 16 in + 16 out + 1 self

// GEMM tiling
#define MTILE   128
#define NTILE   256
#define BK      64                         // fp16 per K-chunk (128B rows)
#define NCHUNK  (KA / BK)                  // 4
#define A_STAGE (MTILE * 128)              // 16KB
#define SMEM_B_OFF (2 * A_STAGE)           // 32KB
#define B_SLAB  (NTILE * 128)              // 32KB per 64-k slab
#define SMEM_TOTAL (SMEM_B_OFF + 4 * B_SLAB)   // 163840

// ---------------------------------------------------------------------------
// Scratch (device globals: allocation-free rule)
// ---------------------------------------------------------------------------
__device__ __align__(16) __half g_xa[(size_t)N_ * KA];            // [N,256] fp16 x
__device__ __align__(16) __half g_wb[(size_t)NMAT * U_ * KB];     // [33][u][256] fp16 w^T
__device__ __align__(16) __half g_all_in [(size_t)L_ * N_ * U_];  // fp16 potentials
__device__ __align__(16) __half g_all_out[(size_t)L_ * N_ * U_];
__device__ __align__(16) __half g_same[(size_t)N_ * U_];
__device__ float g_gin[N_], g_gout[N_], g_gloop[N_];
__device__ int   g_ein[E_], g_lin[E_], g_eout[E_], g_lout[E_];

// ---------------------------------------------------------------------------
// PTX helpers (sm_80+-portable only)
// ---------------------------------------------------------------------------
__device__ __forceinline__ uint32_t smem_u32(const void* p) {
    uint32_t a;
    asm("{ .reg .u64 t; cvta.to.shared.u64 t, %1; cvt.u32.u64 %0, t; }" : "=r"(a) : "l"(p));
    return a;
}
__device__ __forceinline__ void cp_async16(uint32_t dst, const void* src) {
    asm volatile("cp.async.cg.shared.global [%0], [%1], 16;" :: "r"(dst), "l"(src) : "memory");
}
#define CP_COMMIT() asm volatile("cp.async.commit_group;" ::: "memory")

__device__ __forceinline__ uint32_t swz128(uint32_t off) {
    return off ^ ((off >> 3) & 0x70);
}
__device__ __forceinline__ void ldmatrix_x4(uint32_t* r, uint32_t addr) {
    asm volatile("ldmatrix.sync.aligned.m8n8.x4.shared.b16 {%0,%1,%2,%3}, [%4];"
                 : "=r"(r[0]), "=r"(r[1]), "=r"(r[2]), "=r"(r[3]) : "r"(addr));
}
__device__ __forceinline__ void ldmatrix_x2(uint32_t* r, uint32_t addr) {
    asm volatile("ldmatrix.sync.aligned.m8n8.x2.shared.b16 {%0,%1}, [%2];"
                 : "=r"(r[0]), "=r"(r[1]) : "r"(addr));
}
__device__ __forceinline__ void mma_f16(float* c, const uint32_t* a, const uint32_t* b) {
    asm volatile(
        "mma.sync.aligned.m16n8k16.row.col.f32.f16.f16.f32 "
        "{%0,%1,%2,%3}, {%4,%5,%6,%7}, {%8,%9}, {%0,%1,%2,%3};"
        : "+f"(c[0]), "+f"(c[1]), "+f"(c[2]), "+f"(c[3])
        : "r"(a[0]), "r"(a[1]), "r"(a[2]), "r"(a[3]), "r"(b[0]), "r"(b[1]));
}

// ---------------------------------------------------------------------------
// 1) fp16 A operand: xa[n,d] = fp16(src[s,b,d]), n = b*S+s
// ---------------------------------------------------------------------------
__global__ void prep_x_kernel(const float* __restrict__ src) {
    int n = blockIdx.x;
    int s = n & (S_ - 1);
    int b = n >> 8;
    int t = threadIdx.x;
    float x = src[(size_t)s * B_ * D_ + (size_t)b * D_ + t];
    g_xa[(size_t)n * KA + t] = __float2half(x);
}

// ---------------------------------------------------------------------------
// 1b) Transpose weights to [u][d], fp16
// ---------------------------------------------------------------------------
__global__ void prep_w_kernel(const float* __restrict__ Vin,
                              const float* __restrict__ Vout,
                              const float* __restrict__ Ws) {
    int z = blockIdx.z;
    const float* W;
    if (z < L_)          W = Vin  + (size_t)z * D_ * U_;
    else if (z < 2 * L_) W = Vout + (size_t)(z - L_) * D_ * U_;
    else                 W = Ws;

    __shared__ float tile[32][33];
    int d0 = blockIdx.y * 32, u0 = blockIdx.x * 32;
    int tx = threadIdx.x, ty = threadIdx.y;
    #pragma unroll
    for (int j = 0; j < 32; j += 8)
        tile[ty + j][tx] = W[(size_t)(d0 + ty + j) * U_ + u0 + tx];
    __syncthreads();
    __half* base = g_wb + (size_t)z * U_ * KB;
    #pragma unroll
    for (int j = 0; j < 32; j += 8) {
        int u = u0 + ty + j, d = d0 + tx;
        base[(size_t)u * KB + d] = __float2half(tile[tx][ty + j]);
    }
}

// ---------------------------------------------------------------------------
// 2) Edge decode (handles int64-or-int32 materialization)
// ---------------------------------------------------------------------------
__device__ __forceinline__ int detect_is64(const int* p) {
    int z = 1;
    #pragma unroll
    for (int i = 1; i < 128; i += 2) z &= (p[i] == 0);
    return z;
}
__global__ void prep_edges_kernel(const void* __restrict__ arc_in,
                                  const void* __restrict__ lab_in,
                                  const void* __restrict__ arc_out,
                                  const void* __restrict__ lab_out) {
    __shared__ int s64;
    if (threadIdx.x == 0) s64 = detect_is64((const int*)arc_in);
    __syncthreads();
    int e = blockIdx.x * blockDim.x + threadIdx.x;
    if (e >= E_) return;
    int bi, si, li, bo, so, lo;
    if (s64) {
        const long long* ai = (const long long*)arc_in;
        const long long* ao = (const long long*)arc_out;
        bi = (int)ai[e];  si = (int)ai[E_ + e];  li = (int)((const long long*)lab_in)[e];
        bo = (int)ao[e];  so = (int)ao[E_ + e];  lo = (int)((const long long*)lab_out)[e];
    } else {
        const int* ai = (const int*)arc_in;
        const int* ao = (const int*)arc_out;
        bi = ai[e];  si = ai[E_ + e];  li = ((const int*)lab_in)[e];
        bo = ao[e];  so = ao[E_ + e];  lo = ((const int*)lab_out)[e];
    }
    g_ein[e]  = bi * S_ + si;  g_lin[e]  = li;
    g_eout[e] = bo * S_ + so;  g_lout[e] = lo;
}

// ---------------------------------------------------------------------------
// 3) Per-node gate dot products (fp32, exact) — reads src directly
// ---------------------------------------------------------------------------
__global__ void gates_kernel(const float* __restrict__ src,
                             const float* __restrict__ vgin,
                             const float* __restrict__ vgout,
                             const float* __restrict__ wgloop) {
    int gid  = blockIdx.x * blockDim.x + threadIdx.x;
    int warp = gid >> 5;
    int lane = threadIdx.x & 31;
    if (warp >= N_) return;
    int s = warp & (S_ - 1);
    int b = warp >> 8;
    const float* xr = src + (size_t)s * B_ * D_ + (size_t)b * D_;
    float a = 0.f, bb = 0.f, c = 0.f;
    #pragma unroll
    for (int d = lane; d < D_; d += 32) {
        float xv = xr[d];
        a  += xv * vgin[d];
        bb += xv * vgout[d];
        c  += xv * wgloop[d];
    }
    #pragma unroll
    for (int off = 16; off; off >>= 1) {
        a  += __shfl_xor_sync(0xffffffffu, a, off);
        bb += __shfl_xor_sync(0xffffffffu, bb, off);
        c  += __shfl_xor_sync(0xffffffffu, c, off);
    }
    if (lane == 0) { g_gin[warp] = a; g_gout[warp] = bb; g_gloop[warp] = c; }
}

// ---------------------------------------------------------------------------
// 4) mma.sync fp16 GEMM: C[mat] = x16(8192x256) @ w16[mat]^T, fp16 output
//    CTA 128x256, 8 warps (2m x 4n), warp tile 64x64.
//    B (128KB) resident in smem; A double-buffered 64-k chunks.
// ---------------------------------------------------------------------------
__device__ __forceinline__ void load_a_chunk(uint32_t sbase, int buf, int kt,
                                             int m0, int t) {
    uint32_t ab = sbase + buf * A_STAGE;
    #pragma unroll
    for (int r = 0; r < 4; r++) {
        int i = r * 256 + t;                  // 1024 16B segments
        int row = i >> 3, seg = i & 7;
        const char* src = (const char*)g_xa +
            (((size_t)(m0 + row) * KA + (size_t)kt * BK) << 1) + seg * 16;
        cp_async16(ab + swz128(row * 128 + seg * 16), src);
    }
}

__global__ void __launch_bounds__(256, 1) gemm_mma_kernel() {
    extern __shared__ char smem[];
    uint32_t sbase = smem_u32(smem);
    const int t = threadIdx.x, wid = t >> 5, lane = t & 31;
    const int wm = wid & 1, wn = wid >> 1;            // 2m x 4n warp grid
    const int mat = blockIdx.y;
    const int m0 = blockIdx.x * MTILE;
    const __half* wrow0 = g_wb + (size_t)mat * U_ * KB;

    // B resident: 4 slabs of 64 k, 256 u-rows each
    #pragma unroll
    for (int s = 0; s < 4; s++) {
        uint32_t bb = sbase + SMEM_B_OFF + s * B_SLAB;
        #pragma unroll
        for (int r = 0; r < 8; r++) {
            int i = r * 256 + t;              // 2048 16B segments per slab
            int row = i >> 3, seg = i & 7;
            const char* src = (const char*)wrow0 +
                (((size_t)row * KB + (size_t)s * BK) << 1) + seg * 16;
            cp_async16(bb + swz128(row * 128 + seg * 16), src);
        }
    }
    load_a_chunk(sbase, 0, 0, m0, t);
    CP_COMMIT();                               // group: all B + A0

    float acc[4][8][4];
    #pragma unroll
    for (int i = 0; i < 4; i++)
        #pragma unroll
        for (int j = 0; j < 8; j++)
            #pragma unroll
            for (int q = 0; q < 4; q++) acc[i][j][q] = 0.f;

    const int a_row = wm * 64 + (lane & 15);
    const int a_cb  = (lane >> 4) * 16;
    const int b_row = wn * 64 + (lane & 7);
    const int b_cb  = ((lane >> 3) & 1) * 16;

    for (int kt = 0; kt < NCHUNK; kt++) {
        const int buf = kt & 1;
        if (kt + 1 < NCHUNK) {
            load_a_chunk(sbase, buf ^ 1, kt + 1, m0, t);
            CP_COMMIT();
            asm volatile("cp.async.wait_group 1;" ::: "memory");
        } else {
            asm volatile("cp.async.wait_group 0;" ::: "memory");
        }
        __syncthreads();

        uint32_t ab = sbase + buf * A_STAGE;
        uint32_t bb = sbase + SMEM_B_OFF + kt * B_SLAB;   // chunk kt <-> slab kt
        #pragma unroll
        for (int ks = 0; ks < 4; ks++) {
            const int kb = ks * 32;
            uint32_t a_frag[4][4], b_frag[8][2];
            #pragma unroll
            for (int mi = 0; mi < 4; mi++)
                ldmatrix_x4(a_frag[mi],
                    ab + swz128((a_row + mi * 16) * 128 + kb + a_cb));
            #pragma unroll
            for (int ni = 0; ni < 8; ni++)
                ldmatrix_x2(b_frag[ni],
                    bb + swz128((b_row + ni * 8) * 128 + kb + b_cb));
            #pragma unroll
            for (int mi = 0; mi < 4; mi++)
                #pragma unroll
                for (int ni = 0; ni < 8; ni++)
                    mma_f16(acc[mi][ni], a_frag[mi], b_frag[ni]);
        }
        __syncthreads();
    }

    __half* C;
    if (mat < L_)            C = g_all_in  + (size_t)mat * N_ * U_;
    else if (mat < 2 * L_)   C = g_all_out + (size_t)(mat - L_) * N_ * U_;
    else                     C = g_same;

    const int r0 = m0 + wm * 64 + (lane >> 2);
    const int c0 = wn * 64 + (lane & 3) * 2;
    #pragma unroll
    for (int mi = 0; mi < 4; mi++) {
        #pragma unroll
        for (int ni = 0; ni < 8; ni++) {
            __half* p0 = C + (size_t)(r0 + mi * 16) * U_ + c0 + ni * 8;
            __half* p1 = p0 + 8 * U_;
            *(__half2*)p0 = __floats2half2_rn(acc[mi][ni][0], acc[mi][ni][1]);
            *(__half2*)p1 = __floats2half2_rn(acc[mi][ni][2], acc[mi][ni][3]);
        }
    }
}

// ---------------------------------------------------------------------------
// 5) Gather + sigmoid-gated reduce + relu + sent_mask + transpose to [S,B,U]
// ---------------------------------------------------------------------------
__device__ __forceinline__ float sigmoidf_(float g) { return 1.f / (1.f + expf(-g)); }

__global__ void gather_kernel(const float* __restrict__ b_in,
                              const float* __restrict__ bg_in,
                              const float* __restrict__ b_out,
                              const float* __restrict__ bg_out,
                              const float* __restrict__ mask_in,
                              const float* __restrict__ mask_out,
                              const float* __restrict__ mask_loop,
                              const float* __restrict__ sent_mask,
                              float* __restrict__ out) {
    const int n = blockIdx.x;
    const int t = threadIdx.x;
    const int s = n & (S_ - 1);
    const int b = n >> 8;

    __shared__ float sp[33];
    __shared__ int   sidx[33];
    __shared__ int   sl[33];

    if (t < 33) {
        float p; int idx = 0, l = 0;
        if (t < 16) {
            int e = n * DEG_ + t;
            idx = g_ein[e]; l = g_lin[e];
            p = sigmoidf_(g_gin[idx] + bg_in[l]) * mask_in[(size_t)n * DEG_ + t];
        } else if (t < 32) {
            int k = t - 16;
            int e = n * DEG_ + k;
            idx = g_eout[e]; l = g_lout[e];
            p = sigmoidf_(g_gout[idx] + bg_out[l]) * mask_out[(size_t)n * DEG_ + k];
        } else {
            p = sigmoidf_(g_gloop[n]) * mask_loop[n];
        }
        sp[t] = p; sidx[t] = idx; sl[t] = l;
    }
    __syncthreads();

    const float sent = sent_mask[(size_t)s * B_ + b];
    float acc = sp[32] * __half2float(g_same[(size_t)n * U_ + t]);
    #pragma unroll
    for (int k = 0; k < 16; k++) {
        int l = sl[k];
        acc += sp[k] * (__half2float(g_all_in[((size_t)l * N_ + sidx[k]) * U_ + t])
                        + b_in[l * U_ + t]);
    }
    #pragma unroll
    for (int k = 16; k < 32; k++) {
        int l = sl[k];
        acc += sp[k] * (__half2float(g_all_out[((size_t)l * N_ + sidx[k]) * U_ + t])
                        + b_out[l * U_ + t]);
    }
    acc = fmaxf(acc, 0.f) * sent;
    out[(size_t)s * B_ * U_ + (size_t)b * U_ + t] = acc;
}

// ---------------------------------------------------------------------------
// Launch
// ---------------------------------------------------------------------------
extern "C" void kernel_launch(void* const* d_in, const int* in_sizes, int n_in,
                              void* d_out, int out_size) {
    const float* src        = (const float*)d_in[0];
    const float* V_in       = (const float*)d_in[1];
    const float* b_in       = (const float*)d_in[2];
    const float* V_in_gate  = (const float*)d_in[3];
    const float* b_in_gate  = (const float*)d_in[4];
    const float* V_out      = (const float*)d_in[5];
    const float* b_out      = (const float*)d_in[6];
    const float* V_out_gate = (const float*)d_in[7];
    const float* b_out_gate = (const float*)d_in[8];
    const float* W_self     = (const float*)d_in[9];
    const float* W_self_g   = (const float*)d_in[10];
    const void*  arc_in     = d_in[11];
    const void*  arc_out    = d_in[12];
    const void*  lab_in     = d_in[13];
    const void*  lab_out    = d_in[14];
    const float* mask_in    = (const float*)d_in[15];
    const float* mask_out   = (const float*)d_in[16];
    const float* mask_loop  = (const float*)d_in[17];
    const float* sent_mask  = (const float*)d_in[18];
    float* out = (float*)d_out;

    cudaFuncSetAttribute(gemm_mma_kernel,
                         cudaFuncAttributeMaxDynamicSharedMemorySize, SMEM_TOTAL);

    prep_x_kernel<<<N_, 256>>>(src);
    prep_w_kernel<<<dim3(8, 8, NMAT), dim3(32, 8)>>>(V_in, V_out, W_self);
    prep_edges_kernel<<<E_ / 256, 256>>>(arc_in, lab_in, arc_out, lab_out);
    gates_kernel<<<N_ / 8, 256>>>(src, V_in_gate, V_out_gate, W_self_g);

    gemm_mma_kernel<<<dim3(N_ / MTILE, NMAT), 256, SMEM_TOTAL>>>();

    gather_kernel<<<N_, U_>>>(b_in, b_in_gate, b_out, b_out_gate,
                              mask_in, mask_out, mask_loop, sent_mask, out);
}

// round 12
// speedup vs baseline: 4.0892x; 1.0650x over previous
#include <cuda_runtime.h>
#include <cuda_bf16.h>
#include <cuda_fp16.h>
#include <cstdint>

// Problem constants
#define B_    32
#define S_    256
#define D_    256
#define U_    256
#define L_    16
#define DEG_  16
#define N_    (B_ * S_)        // 8192
#define E_    (N_ * DEG_)      // 131072
#define KA    256              // fp16 x
#define KB    256              // fp16 w^T
#define NMAT  33               // 16 in + 16 out + 1 self

// GEMM tiling: CTA 128x128, 8 warps (2m x 4n), warp tile 64x32, occ 2
#define MTILE   128
#define NTILE   128
#define BK      64                         // fp16 per K-chunk (128B rows)
#define NCHUNK  (KA / BK)                  // 4
#define STAGE   (MTILE * 128 + NTILE * 128)    // 16KB A + 16KB B = 32768
#define SMEM_TOTAL (2 * STAGE)             // 65536

// ---------------------------------------------------------------------------
// Scratch (device globals: allocation-free rule)
// ---------------------------------------------------------------------------
__device__ __align__(16) __half g_xa[(size_t)N_ * KA];            // [N,256] fp16 x
__device__ __align__(16) __half g_wb[(size_t)NMAT * U_ * KB];     // [33][u][256] fp16 w^T
__device__ __align__(16) __half g_all_in [(size_t)L_ * N_ * U_];  // fp16 potentials
__device__ __align__(16) __half g_all_out[(size_t)L_ * N_ * U_];
__device__ __align__(16) __half g_same[(size_t)N_ * U_];
__device__ float g_gin[N_], g_gout[N_], g_gloop[N_];
__device__ int   g_ein[E_], g_lin[E_], g_eout[E_], g_lout[E_];

// ---------------------------------------------------------------------------
// PTX helpers (sm_80+-portable only)
// ---------------------------------------------------------------------------
__device__ __forceinline__ uint32_t smem_u32(const void* p) {
    uint32_t a;
    asm("{ .reg .u64 t; cvta.to.shared.u64 t, %1; cvt.u32.u64 %0, t; }" : "=r"(a) : "l"(p));
    return a;
}
__device__ __forceinline__ void cp_async16(uint32_t dst, const void* src) {
    asm volatile("cp.async.cg.shared.global [%0], [%1], 16;" :: "r"(dst), "l"(src) : "memory");
}
#define CP_COMMIT() asm volatile("cp.async.commit_group;" ::: "memory")

__device__ __forceinline__ uint32_t swz128(uint32_t off) {
    return off ^ ((off >> 3) & 0x70);
}
__device__ __forceinline__ void ldmatrix_x4(uint32_t* r, uint32_t addr) {
    asm volatile("ldmatrix.sync.aligned.m8n8.x4.shared.b16 {%0,%1,%2,%3}, [%4];"
                 : "=r"(r[0]), "=r"(r[1]), "=r"(r[2]), "=r"(r[3]) : "r"(addr));
}
__device__ __forceinline__ void ldmatrix_x2(uint32_t* r, uint32_t addr) {
    asm volatile("ldmatrix.sync.aligned.m8n8.x2.shared.b16 {%0,%1}, [%2];"
                 : "=r"(r[0]), "=r"(r[1]) : "r"(addr));
}
__device__ __forceinline__ void mma_f16(float* c, const uint32_t* a, const uint32_t* b) {
    asm volatile(
        "mma.sync.aligned.m16n8k16.row.col.f32.f16.f16.f32 "
        "{%0,%1,%2,%3}, {%4,%5,%6,%7}, {%8,%9}, {%0,%1,%2,%3};"
        : "+f"(c[0]), "+f"(c[1]), "+f"(c[2]), "+f"(c[3])
        : "r"(a[0]), "r"(a[1]), "r"(a[2]), "r"(a[3]), "r"(b[0]), "r"(b[1]));
}

// ---------------------------------------------------------------------------
// 1) fp16 A operand: xa[n,d] = fp16(src[s,b,d]), n = b*S+s
// ---------------------------------------------------------------------------
__global__ void prep_x_kernel(const float* __restrict__ src) {
    int n = blockIdx.x;
    int s = n & (S_ - 1);
    int b = n >> 8;
    int t = threadIdx.x;
    float x = src[(size_t)s * B_ * D_ + (size_t)b * D_ + t];
    g_xa[(size_t)n * KA + t] = __float2half(x);
}

// ---------------------------------------------------------------------------
// 1b) Transpose weights to [u][d], fp16
// ---------------------------------------------------------------------------
__global__ void prep_w_kernel(const float* __restrict__ Vin,
                              const float* __restrict__ Vout,
                              const float* __restrict__ Ws) {
    int z = blockIdx.z;
    const float* W;
    if (z < L_)          W = Vin  + (size_t)z * D_ * U_;
    else if (z < 2 * L_) W = Vout + (size_t)(z - L_) * D_ * U_;
    else                 W = Ws;

    __shared__ float tile[32][33];
    int d0 = blockIdx.y * 32, u0 = blockIdx.x * 32;
    int tx = threadIdx.x, ty = threadIdx.y;
    #pragma unroll
    for (int j = 0; j < 32; j += 8)
        tile[ty + j][tx] = W[(size_t)(d0 + ty + j) * U_ + u0 + tx];
    __syncthreads();
    __half* base = g_wb + (size_t)z * U_ * KB;
    #pragma unroll
    for (int j = 0; j < 32; j += 8) {
        int u = u0 + ty + j, d = d0 + tx;
        base[(size_t)u * KB + d] = __float2half(tile[tx][ty + j]);
    }
}

// ---------------------------------------------------------------------------
// 2) Edge decode (handles int64-or-int32 materialization)
// ---------------------------------------------------------------------------
__device__ __forceinline__ int detect_is64(const int* p) {
    int z = 1;
    #pragma unroll
    for (int i = 1; i < 128; i += 2) z &= (p[i] == 0);
    return z;
}
__global__ void prep_edges_kernel(const void* __restrict__ arc_in,
                                  const void* __restrict__ lab_in,
                                  const void* __restrict__ arc_out,
                                  const void* __restrict__ lab_out) {
    __shared__ int s64;
    if (threadIdx.x == 0) s64 = detect_is64((const int*)arc_in);
    __syncthreads();
    int e = blockIdx.x * blockDim.x + threadIdx.x;
    if (e >= E_) return;
    int bi, si, li, bo, so, lo;
    if (s64) {
        const long long* ai = (const long long*)arc_in;
        const long long* ao = (const long long*)arc_out;
        bi = (int)ai[e];  si = (int)ai[E_ + e];  li = (int)((const long long*)lab_in)[e];
        bo = (int)ao[e];  so = (int)ao[E_ + e];  lo = (int)((const long long*)lab_out)[e];
    } else {
        const int* ai = (const int*)arc_in;
        const int* ao = (const int*)arc_out;
        bi = ai[e];  si = ai[E_ + e];  li = ((const int*)lab_in)[e];
        bo = ao[e];  so = ao[E_ + e];  lo = ((const int*)lab_out)[e];
    }
    g_ein[e]  = bi * S_ + si;  g_lin[e]  = li;
    g_eout[e] = bo * S_ + so;  g_lout[e] = lo;
}

// ---------------------------------------------------------------------------
// 3) Per-node gate dot products (fp32, exact) — reads src directly
// ---------------------------------------------------------------------------
__global__ void gates_kernel(const float* __restrict__ src,
                             const float* __restrict__ vgin,
                             const float* __restrict__ vgout,
                             const float* __restrict__ wgloop) {
    int gid  = blockIdx.x * blockDim.x + threadIdx.x;
    int warp = gid >> 5;
    int lane = threadIdx.x & 31;
    if (warp >= N_) return;
    int s = warp & (S_ - 1);
    int b = warp >> 8;
    const float* xr = src + (size_t)s * B_ * D_ + (size_t)b * D_;
    float a = 0.f, bb = 0.f, c = 0.f;
    #pragma unroll
    for (int d = lane; d < D_; d += 32) {
        float xv = xr[d];
        a  += xv * vgin[d];
        bb += xv * vgout[d];
        c  += xv * wgloop[d];
    }
    #pragma unroll
    for (int off = 16; off; off >>= 1) {
        a  += __shfl_xor_sync(0xffffffffu, a, off);
        bb += __shfl_xor_sync(0xffffffffu, bb, off);
        c  += __shfl_xor_sync(0xffffffffu, c, off);
    }
    if (lane == 0) { g_gin[warp] = a; g_gout[warp] = bb; g_gloop[warp] = c; }
}

// ---------------------------------------------------------------------------
// 4) mma.sync fp16 GEMM: C[mat] = x16(8192x256) @ w16[mat]^T, fp16 output
//    CTA 128x128, 8 warps (2m x 4n), warp tile 64x32, 2 CTAs/SM,
//    (A,B) chunk pairs double-buffered.
// ---------------------------------------------------------------------------
__device__ __forceinline__ void load_stage(uint32_t sbase, int buf, int kt,
                                           const __half* wrow0, int m0, int t) {
    uint32_t ab = sbase + buf * STAGE;
    uint32_t bb = ab + MTILE * 128;
    #pragma unroll
    for (int r = 0; r < 4; r++) {
        int i = r * 256 + t;                  // 1024 16B segments (A)
        int row = i >> 3, seg = i & 7;
        const char* src = (const char*)g_xa +
            (((size_t)(m0 + row) * KA + (size_t)kt * BK) << 1) + seg * 16;
        cp_async16(ab + swz128(row * 128 + seg * 16), src);
    }
    #pragma unroll
    for (int r = 0; r < 4; r++) {
        int i = r * 256 + t;                  // 1024 16B segments (B)
        int row = i >> 3, seg = i & 7;
        const char* src = (const char*)wrow0 +
            (((size_t)row * KB + (size_t)kt * BK) << 1) + seg * 16;
        cp_async16(bb + swz128(row * 128 + seg * 16), src);
    }
}

__global__ void __launch_bounds__(256, 2) gemm_mma_kernel() {
    extern __shared__ char smem[];
    uint32_t sbase = smem_u32(smem);
    const int t = threadIdx.x, wid = t >> 5, lane = t & 31;
    const int wm = wid & 1, wn = wid >> 1;            // 2m x 4n warp grid
    const int mat = blockIdx.z;
    const int m0 = blockIdx.x * MTILE, n0 = blockIdx.y * NTILE;
    const __half* wrow0 = g_wb + (size_t)mat * U_ * KB + (size_t)n0 * KB;

    float acc[4][4][4];
    #pragma unroll
    for (int i = 0; i < 4; i++)
        #pragma unroll
        for (int j = 0; j < 4; j++)
            #pragma unroll
            for (int q = 0; q < 4; q++) acc[i][j][q] = 0.f;

    load_stage(sbase, 0, 0, wrow0, m0, t);
    CP_COMMIT();

    const int a_row = wm * 64 + (lane & 15);
    const int a_cb  = (lane >> 4) * 16;
    const int b_row = wn * 32 + (lane & 7);
    const int b_cb  = ((lane >> 3) & 1) * 16;

    for (int kt = 0; kt < NCHUNK; kt++) {
        const int buf = kt & 1;
        if (kt + 1 < NCHUNK) {
            load_stage(sbase, buf ^ 1, kt + 1, wrow0, m0, t);
            CP_COMMIT();
            asm volatile("cp.async.wait_group 1;" ::: "memory");
        } else {
            asm volatile("cp.async.wait_group 0;" ::: "memory");
        }
        __syncthreads();

        uint32_t ab = sbase + buf * STAGE;
        uint32_t bb = ab + MTILE * 128;
        #pragma unroll
        for (int ks = 0; ks < 4; ks++) {
            const int kb = ks * 32;
            uint32_t a_frag[4][4], b_frag[4][2];
            #pragma unroll
            for (int mi = 0; mi < 4; mi++)
                ldmatrix_x4(a_frag[mi],
                    ab + swz128((a_row + mi * 16) * 128 + kb + a_cb));
            #pragma unroll
            for (int ni = 0; ni < 4; ni++)
                ldmatrix_x2(b_frag[ni],
                    bb + swz128((b_row + ni * 8) * 128 + kb + b_cb));
            #pragma unroll
            for (int mi = 0; mi < 4; mi++)
                #pragma unroll
                for (int ni = 0; ni < 4; ni++)
                    mma_f16(acc[mi][ni], a_frag[mi], b_frag[ni]);
        }
        __syncthreads();
    }

    __half* C;
    if (mat < L_)            C = g_all_in  + (size_t)mat * N_ * U_;
    else if (mat < 2 * L_)   C = g_all_out + (size_t)(mat - L_) * N_ * U_;
    else                     C = g_same;

    const int r0 = m0 + wm * 64 + (lane >> 2);
    const int c0 = n0 + wn * 32 + (lane & 3) * 2;
    #pragma unroll
    for (int mi = 0; mi < 4; mi++) {
        #pragma unroll
        for (int ni = 0; ni < 4; ni++) {
            __half* p0 = C + (size_t)(r0 + mi * 16) * U_ + c0 + ni * 8;
            __half* p1 = p0 + 8 * U_;
            *(__half2*)p0 = __floats2half2_rn(acc[mi][ni][0], acc[mi][ni][1]);
            *(__half2*)p1 = __floats2half2_rn(acc[mi][ni][2], acc[mi][ni][3]);
        }
    }
}

// ---------------------------------------------------------------------------
// 5) Gather + sigmoid-gated reduce + relu + sent_mask + transpose to [S,B,U]
// ---------------------------------------------------------------------------
__device__ __forceinline__ float sigmoidf_(float g) { return 1.f / (1.f + expf(-g)); }

__global__ void gather_kernel(const float* __restrict__ b_in,
                              const float* __restrict__ bg_in,
                              const float* __restrict__ b_out,
                              const float* __restrict__ bg_out,
                              const float* __restrict__ mask_in,
                              const float* __restrict__ mask_out,
                              const float* __restrict__ mask_loop,
                              const float* __restrict__ sent_mask,
                              float* __restrict__ out) {
    const int n = blockIdx.x;
    const int t = threadIdx.x;
    const int s = n & (S_ - 1);
    const int b = n >> 8;

    __shared__ float sp[33];
    __shared__ int   sidx[33];
    __shared__ int   sl[33];

    if (t < 33) {
        float p; int idx = 0, l = 0;
        if (t < 16) {
            int e = n * DEG_ + t;
            idx = g_ein[e]; l = g_lin[e];
            p = sigmoidf_(g_gin[idx] + bg_in[l]) * mask_in[(size_t)n * DEG_ + t];
        } else if (t < 32) {
            int k = t - 16;
            int e = n * DEG_ + k;
            idx = g_eout[e]; l = g_lout[e];
            p = sigmoidf_(g_gout[idx] + bg_out[l]) * mask_out[(size_t)n * DEG_ + k];
        } else {
            p = sigmoidf_(g_gloop[n]) * mask_loop[n];
        }
        sp[t] = p; sidx[t] = idx; sl[t] = l;
    }
    __syncthreads();

    const float sent = sent_mask[(size_t)s * B_ + b];
    float acc = sp[32] * __half2float(g_same[(size_t)n * U_ + t]);
    #pragma unroll
    for (int k = 0; k < 16; k++) {
        int l = sl[k];
        acc += sp[k] * (__half2float(g_all_in[((size_t)l * N_ + sidx[k]) * U_ + t])
                        + b_in[l * U_ + t]);
    }
    #pragma unroll
    for (int k = 16; k < 32; k++) {
        int l = sl[k];
        acc += sp[k] * (__half2float(g_all_out[((size_t)l * N_ + sidx[k]) * U_ + t])
                        + b_out[l * U_ + t]);
    }
    acc = fmaxf(acc, 0.f) * sent;
    out[(size_t)s * B_ * U_ + (size_t)b * U_ + t] = acc;
}

// ---------------------------------------------------------------------------
// Launch
// ---------------------------------------------------------------------------
extern "C" void kernel_launch(void* const* d_in, const int* in_sizes, int n_in,
                              void* d_out, int out_size) {
    const float* src        = (const float*)d_in[0];
    const float* V_in       = (const float*)d_in[1];
    const float* b_in       = (const float*)d_in[2];
    const float* V_in_gate  = (const float*)d_in[3];
    const float* b_in_gate  = (const float*)d_in[4];
    const float* V_out      = (const float*)d_in[5];
    const float* b_out      = (const float*)d_in[6];
    const float* V_out_gate = (const float*)d_in[7];
    const float* b_out_gate = (const float*)d_in[8];
    const float* W_self     = (const float*)d_in[9];
    const float* W_self_g   = (const float*)d_in[10];
    const void*  arc_in     = d_in[11];
    const void*  arc_out    = d_in[12];
    const void*  lab_in     = d_in[13];
    const void*  lab_out    = d_in[14];
    const float* mask_in    = (const float*)d_in[15];
    const float* mask_out   = (const float*)d_in[16];
    const float* mask_loop  = (const float*)d_in[17];
    const float* sent_mask  = (const float*)d_in[18];
    float* out = (float*)d_out;

    cudaFuncSetAttribute(gemm_mma_kernel,
                         cudaFuncAttributeMaxDynamicSharedMemorySize, SMEM_TOTAL);

    prep_x_kernel<<<N_, 256>>>(src);
    prep_w_kernel<<<dim3(8, 8, NMAT), dim3(32, 8)>>>(V_in, V_out, W_self);
    prep_edges_kernel<<<E_ / 256, 256>>>(arc_in, lab_in, arc_out, lab_out);
    gates_kernel<<<N_ / 8, 256>>>(src, V_in_gate, V_out_gate, W_self_g);

    gemm_mma_kernel<<<dim3(N_ / MTILE, U_ / NTILE, NMAT), 256, SMEM_TOTAL>>>();

    gather_kernel<<<N_, U_>>>(b_in, b_in_gate, b_out, b_out_gate,
                              mask_in, mask_out, mask_loop, sent_mask, out);
}